// round 6
// baseline (speedup 1.0000x reference)
#include <cuda_runtime.h>
#include <cuda_bf16.h>
#include <cstdint>

// Problem constants
#define Bb   8
#define Mm   512
#define Ll   1024
#define Hh   512
#define Kk   8
#define Dd   64
#define SKk  1536           // M + L
#define BKC  64             // B * K
#define SCALE 0.125f

// Scratch (device globals)
__device__ float gq[(size_t)BKC * Mm * Dd];      // [bk][s][d]
__device__ float gk[(size_t)BKC * SKk * Dd];     // [bk][s][d]
__device__ float gv[(size_t)BKC * Dd * SKk];     // [bk][d][s]  (transposed)
__device__ float gpe[Ll * Dd];                   // [j][d]
__device__ float g_ctx[(size_t)Bb * Mm * Hh];    // [B, M, K, D]

__device__ __forceinline__ float to_tf32(float x) {
    uint32_t r;
    asm("cvt.rna.tf32.f32 %0, %1;" : "=r"(r) : "f"(x));
    return __uint_as_float(r);
}
__device__ __forceinline__ uint32_t rna_u(float x) {
    uint32_t r;
    asm("cvt.rna.tf32.f32 %0, %1;" : "=r"(r) : "f"(x));
    return r;
}

#define MMA_TF32(c, a0, a1, a2, a3, b0, b1)                                   \
    asm volatile(                                                             \
        "mma.sync.aligned.m16n8k8.row.col.f32.tf32.tf32.f32 "                 \
        "{%0,%1,%2,%3},{%4,%5,%6,%7},{%8,%9},{%0,%1,%2,%3};"                  \
        : "+f"(c[0]), "+f"(c[1]), "+f"(c[2]), "+f"(c[3])                      \
        : "r"(a0), "r"(a1), "r"(a2), "r"(a3), "r"(b0), "r"(b1));

#define PJSTR 36

// ---------------------------------------------------------------------------
// Single-pass tf32 QKV projection GEMM: Y = X @ W^T, head-split stores.
// ---------------------------------------------------------------------------
__global__ __launch_bounds__(256) void proj_qkv_kernel(
        const float* __restrict__ X, const float* __restrict__ W,
        int S, int sel) {
    __shared__ float Xs[128 * PJSTR];
    __shared__ float Ws[128 * PJSTR];

    const int tid  = threadIdx.x;
    const int lane = tid & 31;
    const int wid  = tid >> 5;
    const int warp_m = wid >> 1;
    const int warp_n = wid & 1;
    const int gid = lane >> 2;
    const int tig = lane & 3;
    const int row0 = blockIdx.x * 128;
    const int col0 = blockIdx.y * 128;

    float c[2][8][4];
#pragma unroll
    for (int f = 0; f < 2; f++)
#pragma unroll
        for (int j = 0; j < 8; j++)
#pragma unroll
            for (int t = 0; t < 4; t++) c[f][j][t] = 0.f;

    for (int k0 = 0; k0 < 512; k0 += 32) {
#pragma unroll
        for (int i = 0; i < 4; i++) {
            int f4 = tid + i * 256;
            int r  = f4 >> 3;
            int kq = (f4 & 7) << 2;
            float4 xv = *(const float4*)(X + (size_t)(row0 + r) * 512 + k0 + kq);
            *(float4*)&Xs[r * PJSTR + kq] = xv;
            float4 wv = *(const float4*)(W + (size_t)(col0 + r) * 512 + k0 + kq);
            *(float4*)&Ws[r * PJSTR + kq] = wv;
        }
        __syncthreads();

#pragma unroll
        for (int kk = 0; kk < 32; kk += 8) {
            uint32_t a[2][4];
#pragma unroll
            for (int f = 0; f < 2; f++) {
                int rbase = warp_m * 32 + f * 16 + gid;
#pragma unroll
                for (int rg = 0; rg < 4; rg++) {
                    int r    = rbase + ((rg & 1) << 3);
                    int kcol = kk + tig + ((rg >> 1) << 2);
                    a[f][rg] = rna_u(Xs[r * PJSTR + kcol]);
                }
            }
#pragma unroll
            for (int j = 0; j < 8; j++) {
                int cidx = warp_n * 64 + j * 8 + gid;
                uint32_t b0 = rna_u(Ws[cidx * PJSTR + kk + tig]);
                uint32_t b1 = rna_u(Ws[cidx * PJSTR + kk + tig + 4]);
#pragma unroll
                for (int f = 0; f < 2; f++)
                    MMA_TF32(c[f][j], a[f][0], a[f][1], a[f][2], a[f][3], b0, b1);
            }
        }
        __syncthreads();
    }

#pragma unroll
    for (int f = 0; f < 2; f++) {
        int rloc = warp_m * 32 + f * 16 + gid;
#pragma unroll
        for (int j = 0; j < 8; j++) {
            int cc = col0 + warp_n * 64 + j * 8 + 2 * tig;
#pragma unroll
            for (int h = 0; h < 2; h++) {
                int r = row0 + rloc + h * 8;
                int b = r / S, s = r - b * S;
                int kh = cc >> 6, d = cc & 63;
                int bk = b * Kk + kh;
                float tx = to_tf32(c[f][j][h * 2]);
                float ty = to_tf32(c[f][j][h * 2 + 1]);
                if (sel == 0) {
                    *(float2*)&gq[((size_t)bk * Mm + s) * Dd + d] = make_float2(tx, ty);
                } else if (sel == 1) {
                    *(float2*)&gk[((size_t)bk * SKk + s) * Dd + d] = make_float2(tx, ty);
                } else {
                    gv[((size_t)bk * Dd + d) * SKk + s]     = tx;
                    gv[((size_t)bk * Dd + d + 1) * SKk + s] = ty;
                }
            }
        }
    }
}

// ---------------------------------------------------------------------------
// 3-pass split-tf32 output GEMM: out = g_ctx @ Wo^T  (precision anchor)
// ---------------------------------------------------------------------------
__global__ __launch_bounds__(256) void proj_out_kernel(
        const float* __restrict__ W, float* __restrict__ Yout) {
    __shared__ float Xs[128 * PJSTR];
    __shared__ float Ws[128 * PJSTR];

    const int tid  = threadIdx.x;
    const int lane = tid & 31;
    const int wid  = tid >> 5;
    const int warp_m = wid >> 1;
    const int warp_n = wid & 1;
    const int gid = lane >> 2;
    const int tig = lane & 3;
    const int row0 = blockIdx.x * 128;
    const int col0 = blockIdx.y * 128;

    float c[2][8][4];
#pragma unroll
    for (int f = 0; f < 2; f++)
#pragma unroll
        for (int j = 0; j < 8; j++)
#pragma unroll
            for (int t = 0; t < 4; t++) c[f][j][t] = 0.f;

    for (int k0 = 0; k0 < 512; k0 += 32) {
#pragma unroll
        for (int i = 0; i < 4; i++) {
            int f4 = tid + i * 256;
            int r  = f4 >> 3;
            int kq = (f4 & 7) << 2;
            float4 xv = *(const float4*)(g_ctx + (size_t)(row0 + r) * 512 + k0 + kq);
            *(float4*)&Xs[r * PJSTR + kq] = xv;
            float4 wv = *(const float4*)(W + (size_t)(col0 + r) * 512 + k0 + kq);
            *(float4*)&Ws[r * PJSTR + kq] = wv;
        }
        __syncthreads();

#pragma unroll
        for (int kk = 0; kk < 32; kk += 8) {
            uint32_t ahi[2][4], alo[2][4];
#pragma unroll
            for (int f = 0; f < 2; f++) {
                int rbase = warp_m * 32 + f * 16 + gid;
#pragma unroll
                for (int rg = 0; rg < 4; rg++) {
                    int r    = rbase + ((rg & 1) << 3);
                    int kcol = kk + tig + ((rg >> 1) << 2);
                    float x  = Xs[r * PJSTR + kcol];
                    uint32_t hb = __float_as_uint(x) & 0xFFFFE000u;
                    ahi[f][rg] = hb;
                    alo[f][rg] = __float_as_uint(x - __uint_as_float(hb));
                }
            }
#pragma unroll
            for (int j = 0; j < 8; j++) {
                int cidx = warp_n * 64 + j * 8 + gid;
                float b0f = Ws[cidx * PJSTR + kk + tig];
                float b1f = Ws[cidx * PJSTR + kk + tig + 4];
                uint32_t b0h = __float_as_uint(b0f) & 0xFFFFE000u;
                uint32_t b1h = __float_as_uint(b1f) & 0xFFFFE000u;
                uint32_t b0l = __float_as_uint(b0f - __uint_as_float(b0h));
                uint32_t b1l = __float_as_uint(b1f - __uint_as_float(b1h));
#pragma unroll
                for (int f = 0; f < 2; f++) {
                    MMA_TF32(c[f][j], ahi[f][0], ahi[f][1], ahi[f][2], ahi[f][3], b0h, b1h);
                    MMA_TF32(c[f][j], ahi[f][0], ahi[f][1], ahi[f][2], ahi[f][3], b0l, b1l);
                    MMA_TF32(c[f][j], alo[f][0], alo[f][1], alo[f][2], alo[f][3], b0h, b1h);
                }
            }
        }
        __syncthreads();
    }

#pragma unroll
    for (int f = 0; f < 2; f++) {
        int rloc = warp_m * 32 + f * 16 + gid;
#pragma unroll
        for (int j = 0; j < 8; j++) {
            int cc = col0 + warp_n * 64 + j * 8 + 2 * tig;
#pragma unroll
            for (int h = 0; h < 2; h++) {
                int r = row0 + rloc + h * 8;
                *(float2*)(Yout + (size_t)r * 512 + cc) =
                    make_float2(c[f][j][h * 2], c[f][j][h * 2 + 1]);
            }
        }
    }
}

// ---------------------------------------------------------------------------
// PE transpose prep: gpe[j][d] = tf32(pe[d][j])
// ---------------------------------------------------------------------------
__global__ void pe_prep_kernel(const float* __restrict__ pe) {
    int idx = blockIdx.x * 256 + threadIdx.x;
    if (idx < Ll * Dd) {
        int j = idx >> 6, d = idx & 63;
        gpe[idx] = to_tf32(pe[d * Ll + j]);
    }
}

// ---------------------------------------------------------------------------
// Single-pass tf32 MMA banded attention — 2 CTAs/SM layout (~102 KB smem).
//  * SCALE folded into Q at load (exact in tf32)
//  * Spe merged into Srel (two-phase scatter: pacc write, sync, sacc +=)
//  * V overlays PE region (loaded after MMA phase)
//  * P overlays K region (as before)
// ---------------------------------------------------------------------------
#define QSTR 68
#define KSTR 68
#define VSTR 132
#define PSTR2 132
#define OFF_Q    0
#define OFF_K    (OFF_Q + 64 * QSTR)        // 4352
#define OFF_PEV  (OFF_K + 128 * KSTR)       // 13056
#define OFF_SREL (OFF_PEV + 64 * VSTR)      // 21504
#define OFF_CORR (OFF_SREL + 64 * QSTR)     // 25856
#define OFF_LINV (OFF_CORR + 64)
#define ATTN_SMEM_FLOATS (OFF_LINV + 64)    // 25984 floats = 103,936 B
#define OFF_P    OFF_K                      // P 64x132 = 8448 <= K 8704

__global__ __launch_bounds__(256, 2) void attn_mma_kernel(
        const float* __restrict__ span_val) {
    extern __shared__ float sm[];
    float* Qs   = sm + OFF_Q;
    float* Ks   = sm + OFF_K;
    float* PEs  = sm + OFF_PEV;    // PE during score phase
    float* Vs   = sm + OFF_PEV;    // V during AV phase (overlay)
    float* Srel = sm + OFF_SREL;
    float* corr_s = sm + OFF_CORR;
    float* linv_s = sm + OFF_LINV;
    float* Ps   = sm + OFF_P;

    const uint32_t* Qu  = (const uint32_t*)Qs;
    const uint32_t* Ku  = (const uint32_t*)Ks;
    const uint32_t* Vu  = (const uint32_t*)Vs;
    const uint32_t* PEu = (const uint32_t*)PEs;
    const uint32_t* Pu  = (const uint32_t*)Ps;

    const int tid  = threadIdx.x;
    const int lane = tid & 31;
    const int wid  = tid >> 5;
    const int gid  = lane >> 2;
    const int tig  = lane & 3;
    const int bk   = blockIdx.y;
    const int i0   = blockIdx.x * 64;
    const int kh   = bk & 7;

    const int m0  = (wid & 3) * 16;
    const int nq0 = (wid >> 2) * 64;
    const int np0 = (wid >> 2) * 32;

    const int srow = tid >> 2;
    const int tg4  = tid & 3;
    const int tbase = tg4 * 16;
    const float spanL = span_val[kh] * 1024.f;

    // Q tile (pre-scaled by SCALE; exact power of 2 in tf32)
    {
        const float* gqp = gq + ((size_t)bk * Mm + i0) * Dd;
#pragma unroll
        for (int it = 0; it < 4; it++) {
            int idx = tid + it * 256;
            int r = idx >> 4, c4 = (idx & 15) << 2;
            float4 v = *(const float4*)(gqp + (size_t)r * Dd + c4);
            v.x *= SCALE; v.y *= SCALE; v.z *= SCALE; v.w *= SCALE;
            *(float4*)&Qs[r * QSTR + c4] = v;
        }
    }

    float oacc[4][4];
#pragma unroll
    for (int j = 0; j < 4; j++)
#pragma unroll
        for (int t = 0; t < 4; t++) oacc[j][t] = 0.f;

    float m_run = -1e30f, l_run = 0.f;

    for (int jc = 0; jc < Ll; jc += 64) {
        __syncthreads();                    // S0: protect K/P, PE/V vs prev AV
        // stage K (128x64) and PE (64x64)
        {
            const float* gkp = gk + ((size_t)bk * SKk + i0 + jc) * Dd;
#pragma unroll
            for (int it = 0; it < 8; it++) {
                int idx = tid + it * 256;
                int r = idx >> 4, c4 = (idx & 15) << 2;
                *(float4*)&Ks[r * KSTR + c4] = *(const float4*)(gkp + (size_t)r * Dd + c4);
            }
            const float* gpp = gpe + (size_t)jc * Dd;
#pragma unroll
            for (int it = 0; it < 4; it++) {
                int idx = tid + it * 256;
                int r = idx >> 4, c4 = (idx & 15) << 2;
                *(float4*)&PEs[r * QSTR + c4] = *(const float4*)(gpp + (size_t)r * Dd + c4);
            }
        }
        __syncthreads();                    // S1

        // ---- QK^T (64x128) + Q@PE (64x64), single-pass tf32
        float sacc[8][4], pacc[4][4];
#pragma unroll
        for (int j = 0; j < 8; j++)
#pragma unroll
            for (int t = 0; t < 4; t++) sacc[j][t] = 0.f;
#pragma unroll
        for (int j = 0; j < 4; j++)
#pragma unroll
            for (int t = 0; t < 4; t++) pacc[j][t] = 0.f;

#pragma unroll
        for (int k0 = 0; k0 < 64; k0 += 8) {
            int ar = (m0 + gid) * QSTR + k0 + tig;
            uint32_t a0 = Qu[ar];
            uint32_t a1 = Qu[ar + 8 * QSTR];
            uint32_t a2 = Qu[ar + 4];
            uint32_t a3 = Qu[ar + 8 * QSTR + 4];
#pragma unroll
            for (int j = 0; j < 8; j++) {
                int br = (nq0 + 8 * j + gid) * KSTR + k0 + tig;
                MMA_TF32(sacc[j], a0, a1, a2, a3, Ku[br], Ku[br + 4]);
            }
#pragma unroll
            for (int j = 0; j < 4; j++) {
                int br = (np0 + 8 * j + gid) * QSTR + k0 + tig;
                MMA_TF32(pacc[j], a0, a1, a2, a3, PEu[br], PEu[br + 4]);
            }
        }

        // phase 1: PE scores -> Srel (every element written exactly once)
#pragma unroll
        for (int j = 0; j < 4; j++) {
            int col = np0 + 8 * j + 2 * tig;
            Srel[(m0 + gid) * QSTR + col]     = pacc[j][0];
            Srel[(m0 + gid) * QSTR + col + 1] = pacc[j][1];
            Srel[(m0 + gid + 8) * QSTR + col]     = pacc[j][2];
            Srel[(m0 + gid + 8) * QSTR + col + 1] = pacc[j][3];
        }
        __syncthreads();                    // S2: pacc visible; PE region free

        // phase 2: de-skewed QK band += (unique owner per element)
#pragma unroll
        for (int j = 0; j < 8; j++) {
            int col = nq0 + 8 * j + 2 * tig;
            int r0 = m0 + gid, r1 = r0 + 8;
            int t00 = col - r0, t10 = col - r1;
            if ((unsigned)t00 < 64u)       Srel[r0 * QSTR + t00]     += sacc[j][0];
            if ((unsigned)(t00 + 1) < 64u) Srel[r0 * QSTR + t00 + 1] += sacc[j][1];
            if ((unsigned)t10 < 64u)       Srel[r1 * QSTR + t10]     += sacc[j][2];
            if ((unsigned)(t10 + 1) < 64u) Srel[r1 * QSTR + t10 + 1] += sacc[j][3];
        }

        // stage V (64 d x 128 u) into the freed PE region
        {
            const float* gvp = gv + (size_t)bk * Dd * SKk + i0 + jc;
#pragma unroll
            for (int it = 0; it < 8; it++) {
                int idx = tid + it * 256;
                int d = idx >> 5, c4 = (idx & 31) << 2;
                *(float4*)&Vs[d * VSTR + c4] = *(const float4*)(gvp + (size_t)d * SKk + c4);
            }
        }
        __syncthreads();                    // S3: Srel complete

        // ---- online softmax (4 threads per row, 16 t each); P overlays K
        {
            float s[16];
            float mloc = -1e30f;
#pragma unroll
            for (int e = 0; e < 16; e++) {
                s[e] = Srel[srow * QSTR + tbase + e];
                mloc = fmaxf(mloc, s[e]);
            }
            mloc = fmaxf(mloc, __shfl_xor_sync(0xFFFFFFFFu, mloc, 1));
            mloc = fmaxf(mloc, __shfl_xor_sync(0xFFFFFFFFu, mloc, 2));
            float m_new = fmaxf(m_run, mloc);
            float corr  = __expf(m_run - m_new);
            l_run *= corr;
            float p[16], psum = 0.f;
#pragma unroll
            for (int e = 0; e < 16; e++) { p[e] = __expf(s[e] - m_new); psum += p[e]; }
            psum += __shfl_xor_sync(0xFFFFFFFFu, psum, 1);
            psum += __shfl_xor_sync(0xFFFFFFFFu, psum, 2);
            l_run += psum;
            m_run = m_new;
            if (tg4 == 0) corr_s[srow] = corr;

#pragma unroll
            for (int e = 0; e < 16; e++) {
                int t = tbase + e;
                float jj = (float)(jc + t);
                float mk = fminf(1.f, fmaxf(0.f, (jj - 1023.f + spanL) * (1.f / 32.f) + 1.f));
                float pm = to_tf32(p[e] * mk);
                int u = srow + t;
                Ps[srow * PSTR2 + u] = pm;
                int uz = (t < srow) ? t : t + 64;
                Ps[srow * PSTR2 + uz] = 0.f;
            }
        }
        __syncthreads();                    // S4: P and V visible

        // ---- AV: oacc = oacc*corr + P_abs @ V^T
        {
            float cA = corr_s[m0 + gid], cB = corr_s[m0 + gid + 8];
#pragma unroll
            for (int j = 0; j < 4; j++) {
                oacc[j][0] *= cA; oacc[j][1] *= cA;
                oacc[j][2] *= cB; oacc[j][3] *= cB;
            }
#pragma unroll
            for (int k0 = 0; k0 < 128; k0 += 8) {
                int ar = (m0 + gid) * PSTR2 + k0 + tig;
                uint32_t a0 = Pu[ar];
                uint32_t a1 = Pu[ar + 8 * PSTR2];
                uint32_t a2 = Pu[ar + 4];
                uint32_t a3 = Pu[ar + 8 * PSTR2 + 4];
#pragma unroll
                for (int j = 0; j < 4; j++) {
                    int br = (np0 + 8 * j + gid) * VSTR + k0 + tig;
                    MMA_TF32(oacc[j], a0, a1, a2, a3, Vu[br], Vu[br + 4]);
                }
            }
        }
    }

    __syncthreads();
    if (tg4 == 0) linv_s[srow] = 1.f / l_run;
    __syncthreads();

    // epilogue: g_ctx[b][i0+row][kh][d]
    {
        float lA = linv_s[m0 + gid], lB = linv_s[m0 + gid + 8];
        int b = bk >> 3;
        int r0 = i0 + m0 + gid;
#pragma unroll
        for (int j = 0; j < 4; j++) {
            int col = np0 + 8 * j + 2 * tig;
            float* p0 = g_ctx + ((size_t)(b * Mm + r0) * Kk + kh) * Dd + col;
            float* p1 = g_ctx + ((size_t)(b * Mm + r0 + 8) * Kk + kh) * Dd + col;
            *(float2*)p0 = make_float2(oacc[j][0] * lA, oacc[j][1] * lA);
            *(float2*)p1 = make_float2(oacc[j][2] * lB, oacc[j][3] * lB);
        }
    }
}

// ---------------------------------------------------------------------------
extern "C" void kernel_launch(void* const* d_in, const int* in_sizes, int n_in,
                              void* d_out, int out_size) {
    const float* query = (const float*)d_in[0];
    const float* key   = (const float*)d_in[1];
    const float* value = (const float*)d_in[2];
    const float* pe    = (const float*)d_in[3];
    const float* Wq    = (const float*)d_in[4];
    const float* Wk    = (const float*)d_in[5];
    const float* Wv    = (const float*)d_in[6];
    const float* Wo    = (const float*)d_in[7];
    const float* span  = (const float*)d_in[8];
    float* out = (float*)d_out;

    cudaFuncSetAttribute(attn_mma_kernel,
                         cudaFuncAttributeMaxDynamicSharedMemorySize,
                         ATTN_SMEM_FLOATS * (int)sizeof(float));

    proj_qkv_kernel<<<dim3(Bb * Mm / 128, 4), 256>>>(query, Wq, Mm, 0);
    proj_qkv_kernel<<<dim3(Bb * SKk / 128, 4), 256>>>(key, Wk, SKk, 1);
    proj_qkv_kernel<<<dim3(Bb * SKk / 128, 4), 256>>>(value, Wv, SKk, 2);
    pe_prep_kernel<<<(Ll * Dd + 255) / 256, 256>>>(pe);

    attn_mma_kernel<<<dim3(Mm / 64, BKC), 256,
                      ATTN_SMEM_FLOATS * (int)sizeof(float)>>>(span);

    proj_out_kernel<<<dim3(Bb * Mm / 128, 4), 256>>>(Wo, out);
}

// round 7
// speedup vs baseline: 1.2327x; 1.2327x over previous
#include <cuda_runtime.h>
#include <cuda_bf16.h>
#include <cstdint>

// Problem constants
#define Bb   8
#define Mm   512
#define Ll   1024
#define Hh   512
#define Kk   8
#define Dd   64
#define SKk  1536           // M + L
#define BKC  64             // B * K
#define SCALE 0.125f

// k-group permutation: within each 8-group, k -> (k<4 ? 2k : 2(k-4)+1)
// so (tig, tig+4) become adjacent slots (2*tig, 2*tig+1).
__host__ __device__ __forceinline__ int perm8(int d) {
    return (d & ~7) | (((d & 3) << 1) | ((d >> 2) & 1));
}

// Scratch (device globals) — gq/gk: d-permuted; gv: s-permuted; gpe: d-permuted
__device__ float gq[(size_t)BKC * Mm * Dd];      // [bk][s][d']
__device__ float gk[(size_t)BKC * SKk * Dd];     // [bk][s][d']
__device__ float gv[(size_t)BKC * Dd * SKk];     // [bk][d][s']
__device__ float gpe[Ll * Dd];                   // [j][d']
__device__ float g_ctx[(size_t)Bb * Mm * Hh];    // [B, M, K, D]

__device__ __forceinline__ float to_tf32(float x) {
    uint32_t r;
    asm("cvt.rna.tf32.f32 %0, %1;" : "=r"(r) : "f"(x));
    return __uint_as_float(r);
}
__device__ __forceinline__ uint32_t rna_u(float x) {
    uint32_t r;
    asm("cvt.rna.tf32.f32 %0, %1;" : "=r"(r) : "f"(x));
    return r;
}

#define MMA_TF32(c, a0, a1, a2, a3, b0, b1)                                   \
    asm volatile(                                                             \
        "mma.sync.aligned.m16n8k8.row.col.f32.tf32.tf32.f32 "                 \
        "{%0,%1,%2,%3},{%4,%5,%6,%7},{%8,%9},{%0,%1,%2,%3};"                  \
        : "+f"(c[0]), "+f"(c[1]), "+f"(c[2]), "+f"(c[3])                      \
        : "r"(a0), "r"(a1), "r"(a2), "r"(a3), "r"(b0), "r"(b1));

#define PJSTR 36

// ---------------------------------------------------------------------------
// Single-pass tf32 QKV projection GEMM: Y = X @ W^T, head-split permuted store
// ---------------------------------------------------------------------------
__global__ __launch_bounds__(256) void proj_qkv_kernel(
        const float* __restrict__ X, const float* __restrict__ W,
        int S, int sel) {
    __shared__ float Xs[128 * PJSTR];
    __shared__ float Ws[128 * PJSTR];

    const int tid  = threadIdx.x;
    const int lane = tid & 31;
    const int wid  = tid >> 5;
    const int warp_m = wid >> 1;
    const int warp_n = wid & 1;
    const int gid = lane >> 2;
    const int tig = lane & 3;
    const int row0 = blockIdx.x * 128;
    const int col0 = blockIdx.y * 128;

    float c[2][8][4];
#pragma unroll
    for (int f = 0; f < 2; f++)
#pragma unroll
        for (int j = 0; j < 8; j++)
#pragma unroll
            for (int t = 0; t < 4; t++) c[f][j][t] = 0.f;

    for (int k0 = 0; k0 < 512; k0 += 32) {
#pragma unroll
        for (int i = 0; i < 4; i++) {
            int f4 = tid + i * 256;
            int r  = f4 >> 3;
            int kq = (f4 & 7) << 2;
            float4 xv = *(const float4*)(X + (size_t)(row0 + r) * 512 + k0 + kq);
            *(float4*)&Xs[r * PJSTR + kq] = xv;
            float4 wv = *(const float4*)(W + (size_t)(col0 + r) * 512 + k0 + kq);
            *(float4*)&Ws[r * PJSTR + kq] = wv;
        }
        __syncthreads();

#pragma unroll
        for (int kk = 0; kk < 32; kk += 8) {
            uint32_t a[2][4];
#pragma unroll
            for (int f = 0; f < 2; f++) {
                int rbase = warp_m * 32 + f * 16 + gid;
#pragma unroll
                for (int rg = 0; rg < 4; rg++) {
                    int r    = rbase + ((rg & 1) << 3);
                    int kcol = kk + tig + ((rg >> 1) << 2);
                    a[f][rg] = rna_u(Xs[r * PJSTR + kcol]);
                }
            }
#pragma unroll
            for (int j = 0; j < 8; j++) {
                int cidx = warp_n * 64 + j * 8 + gid;
                uint32_t b0 = rna_u(Ws[cidx * PJSTR + kk + tig]);
                uint32_t b1 = rna_u(Ws[cidx * PJSTR + kk + tig + 4]);
#pragma unroll
                for (int f = 0; f < 2; f++)
                    MMA_TF32(c[f][j], a[f][0], a[f][1], a[f][2], a[f][3], b0, b1);
            }
        }
        __syncthreads();
    }

#pragma unroll
    for (int f = 0; f < 2; f++) {
        int rloc = warp_m * 32 + f * 16 + gid;
#pragma unroll
        for (int j = 0; j < 8; j++) {
            int cc = col0 + warp_n * 64 + j * 8 + 2 * tig;
#pragma unroll
            for (int h = 0; h < 2; h++) {
                int r = row0 + rloc + h * 8;
                int b = r / S, s = r - b * S;
                int kh = cc >> 6, d = cc & 63;
                int bk = b * Kk + kh;
                float tx = to_tf32(c[f][j][h * 2]);
                float ty = to_tf32(c[f][j][h * 2 + 1]);
                int dp0 = perm8(d), dp1 = perm8(d + 1);
                if (sel == 0) {
                    size_t base = ((size_t)bk * Mm + s) * Dd;
                    gq[base + dp0] = tx;
                    gq[base + dp1] = ty;
                } else if (sel == 1) {
                    size_t base = ((size_t)bk * SKk + s) * Dd;
                    gk[base + dp0] = tx;
                    gk[base + dp1] = ty;
                } else {
                    int sp = perm8(s);     // permute position dim for V
                    gv[((size_t)bk * Dd + d) * SKk + sp]     = tx;
                    gv[((size_t)bk * Dd + d + 1) * SKk + sp] = ty;
                }
            }
        }
    }
}

// ---------------------------------------------------------------------------
// 3-pass split-tf32 output GEMM: out = g_ctx @ Wo^T  (precision anchor)
// ---------------------------------------------------------------------------
__global__ __launch_bounds__(256) void proj_out_kernel(
        const float* __restrict__ W, float* __restrict__ Yout) {
    __shared__ float Xs[128 * PJSTR];
    __shared__ float Ws[128 * PJSTR];

    const int tid  = threadIdx.x;
    const int lane = tid & 31;
    const int wid  = tid >> 5;
    const int warp_m = wid >> 1;
    const int warp_n = wid & 1;
    const int gid = lane >> 2;
    const int tig = lane & 3;
    const int row0 = blockIdx.x * 128;
    const int col0 = blockIdx.y * 128;

    float c[2][8][4];
#pragma unroll
    for (int f = 0; f < 2; f++)
#pragma unroll
        for (int j = 0; j < 8; j++)
#pragma unroll
            for (int t = 0; t < 4; t++) c[f][j][t] = 0.f;

    for (int k0 = 0; k0 < 512; k0 += 32) {
#pragma unroll
        for (int i = 0; i < 4; i++) {
            int f4 = tid + i * 256;
            int r  = f4 >> 3;
            int kq = (f4 & 7) << 2;
            float4 xv = *(const float4*)(g_ctx + (size_t)(row0 + r) * 512 + k0 + kq);
            *(float4*)&Xs[r * PJSTR + kq] = xv;
            float4 wv = *(const float4*)(W + (size_t)(col0 + r) * 512 + k0 + kq);
            *(float4*)&Ws[r * PJSTR + kq] = wv;
        }
        __syncthreads();

#pragma unroll
        for (int kk = 0; kk < 32; kk += 8) {
            uint32_t ahi[2][4], alo[2][4];
#pragma unroll
            for (int f = 0; f < 2; f++) {
                int rbase = warp_m * 32 + f * 16 + gid;
#pragma unroll
                for (int rg = 0; rg < 4; rg++) {
                    int r    = rbase + ((rg & 1) << 3);
                    int kcol = kk + tig + ((rg >> 1) << 2);
                    float x  = Xs[r * PJSTR + kcol];
                    uint32_t hb = __float_as_uint(x) & 0xFFFFE000u;
                    ahi[f][rg] = hb;
                    alo[f][rg] = __float_as_uint(x - __uint_as_float(hb));
                }
            }
#pragma unroll
            for (int j = 0; j < 8; j++) {
                int cidx = warp_n * 64 + j * 8 + gid;
                float b0f = Ws[cidx * PJSTR + kk + tig];
                float b1f = Ws[cidx * PJSTR + kk + tig + 4];
                uint32_t b0h = __float_as_uint(b0f) & 0xFFFFE000u;
                uint32_t b1h = __float_as_uint(b1f) & 0xFFFFE000u;
                uint32_t b0l = __float_as_uint(b0f - __uint_as_float(b0h));
                uint32_t b1l = __float_as_uint(b1f - __uint_as_float(b1h));
#pragma unroll
                for (int f = 0; f < 2; f++) {
                    MMA_TF32(c[f][j], ahi[f][0], ahi[f][1], ahi[f][2], ahi[f][3], b0h, b1h);
                    MMA_TF32(c[f][j], ahi[f][0], ahi[f][1], ahi[f][2], ahi[f][3], b0l, b1l);
                    MMA_TF32(c[f][j], alo[f][0], alo[f][1], alo[f][2], alo[f][3], b0h, b1h);
                }
            }
        }
        __syncthreads();
    }

#pragma unroll
    for (int f = 0; f < 2; f++) {
        int rloc = warp_m * 32 + f * 16 + gid;
#pragma unroll
        for (int j = 0; j < 8; j++) {
            int cc = col0 + warp_n * 64 + j * 8 + 2 * tig;
#pragma unroll
            for (int h = 0; h < 2; h++) {
                int r = row0 + rloc + h * 8;
                *(float2*)(Yout + (size_t)r * 512 + cc) =
                    make_float2(c[f][j][h * 2], c[f][j][h * 2 + 1]);
            }
        }
    }
}

// ---------------------------------------------------------------------------
// PE transpose prep: gpe[j][perm(d)] = tf32(pe[d][j])
// ---------------------------------------------------------------------------
__global__ void pe_prep_kernel(const float* __restrict__ pe) {
    int idx = blockIdx.x * 256 + threadIdx.x;
    if (idx < Ll * Dd) {
        int j = idx >> 6, d = idx & 63;
        gpe[(size_t)j * 64 + perm8(d)] = to_tf32(pe[d * Ll + j]);
    }
}

// ---------------------------------------------------------------------------
// Single-pass tf32 MMA banded attention (round-5 structure, 1 CTA/SM)
// + k-permuted smem layout: fragment pairs load as LDS.64
// + SCALE folded into Q load (exact)
// ---------------------------------------------------------------------------
#define QSTR 68
#define KSTR 68
#define VSTR 132
#define PSTR2 132
#define OFF_Q    0
#define OFF_K    (OFF_Q + 64 * QSTR)
#define OFF_V    (OFF_K + 128 * KSTR)
#define OFF_PE   (OFF_V + 64 * VSTR)
#define OFF_SREL (OFF_PE + 64 * QSTR)
#define OFF_SPE  (OFF_SREL + 64 * QSTR)
#define OFF_CORR (OFF_SPE + 64 * QSTR)
#define OFF_LINV (OFF_CORR + 64)
#define ATTN_SMEM_FLOATS (OFF_LINV + 64)
#define OFF_P    OFF_K

__global__ __launch_bounds__(256) void attn_mma_kernel(
        const float* __restrict__ span_val) {
    extern __shared__ float sm[];
    float* Qs   = sm + OFF_Q;
    float* Ks   = sm + OFF_K;
    float* Vs   = sm + OFF_V;
    float* PEs  = sm + OFF_PE;
    float* Srel = sm + OFF_SREL;
    float* Spe  = sm + OFF_SPE;
    float* corr_s = sm + OFF_CORR;
    float* linv_s = sm + OFF_LINV;
    float* Ps   = sm + OFF_P;

    const int tid  = threadIdx.x;
    const int lane = tid & 31;
    const int wid  = tid >> 5;
    const int gid  = lane >> 2;
    const int tig  = lane & 3;
    const int bk   = blockIdx.y;
    const int i0   = blockIdx.x * 64;
    const int kh   = bk & 7;

    const int m0  = (wid & 3) * 16;
    const int nq0 = (wid >> 2) * 64;
    const int np0 = (wid >> 2) * 32;

    const int srow = tid >> 2;
    const int tg4  = tid & 3;
    const int tbase = tg4 * 16;
    const float spanL = span_val[kh] * 1024.f;

    // Q tile (pre-scaled by SCALE; exact power of 2)
    {
        const float* gqp = gq + ((size_t)bk * Mm + i0) * Dd;
#pragma unroll
        for (int it = 0; it < 4; it++) {
            int idx = tid + it * 256;
            int r = idx >> 4, c4 = (idx & 15) << 2;
            float4 v = *(const float4*)(gqp + (size_t)r * Dd + c4);
            v.x *= SCALE; v.y *= SCALE; v.z *= SCALE; v.w *= SCALE;
            *(float4*)&Qs[r * QSTR + c4] = v;
        }
    }

    float oacc[4][4];
#pragma unroll
    for (int j = 0; j < 4; j++)
#pragma unroll
        for (int t = 0; t < 4; t++) oacc[j][t] = 0.f;

    float m_run = -1e30f, l_run = 0.f;

    for (int jc = 0; jc < Ll; jc += 64) {
        __syncthreads();
        {
            const float* gkp = gk + ((size_t)bk * SKk + i0 + jc) * Dd;
#pragma unroll
            for (int it = 0; it < 8; it++) {
                int idx = tid + it * 256;
                int r = idx >> 4, c4 = (idx & 15) << 2;
                *(float4*)&Ks[r * KSTR + c4] = *(const float4*)(gkp + (size_t)r * Dd + c4);
            }
            const float* gvp = gv + (size_t)bk * Dd * SKk + i0 + jc;
#pragma unroll
            for (int it = 0; it < 8; it++) {
                int idx = tid + it * 256;
                int d = idx >> 5, c4 = (idx & 31) << 2;
                *(float4*)&Vs[d * VSTR + c4] = *(const float4*)(gvp + (size_t)d * SKk + c4);
            }
            const float* gpp = gpe + (size_t)jc * Dd;
#pragma unroll
            for (int it = 0; it < 4; it++) {
                int idx = tid + it * 256;
                int r = idx >> 4, c4 = (idx & 15) << 2;
                *(float4*)&PEs[r * QSTR + c4] = *(const float4*)(gpp + (size_t)r * Dd + c4);
            }
        }
        __syncthreads();

        // ---- QK^T (64x128) + Q@PE (64x64), single-pass tf32, LDS.64 frags
        float sacc[8][4], pacc[4][4];
#pragma unroll
        for (int j = 0; j < 8; j++)
#pragma unroll
            for (int t = 0; t < 4; t++) sacc[j][t] = 0.f;
#pragma unroll
        for (int j = 0; j < 4; j++)
#pragma unroll
            for (int t = 0; t < 4; t++) pacc[j][t] = 0.f;

#pragma unroll
        for (int k0 = 0; k0 < 64; k0 += 8) {
            float2 qa = *(const float2*)&Qs[(m0 + gid) * QSTR + k0 + 2 * tig];
            float2 qb = *(const float2*)&Qs[(m0 + gid + 8) * QSTR + k0 + 2 * tig];
            uint32_t a0 = __float_as_uint(qa.x), a2 = __float_as_uint(qa.y);
            uint32_t a1 = __float_as_uint(qb.x), a3 = __float_as_uint(qb.y);
#pragma unroll
            for (int j = 0; j < 8; j++) {
                float2 kb = *(const float2*)&Ks[(nq0 + 8 * j + gid) * KSTR + k0 + 2 * tig];
                MMA_TF32(sacc[j], a0, a1, a2, a3,
                         __float_as_uint(kb.x), __float_as_uint(kb.y));
            }
#pragma unroll
            for (int j = 0; j < 4; j++) {
                float2 pb = *(const float2*)&PEs[(np0 + 8 * j + gid) * QSTR + k0 + 2 * tig];
                MMA_TF32(pacc[j], a0, a1, a2, a3,
                         __float_as_uint(pb.x), __float_as_uint(pb.y));
            }
        }

        // scatter QK rect -> de-skewed Srel[i][col-row]
#pragma unroll
        for (int j = 0; j < 8; j++) {
            int col = nq0 + 8 * j + 2 * tig;
            int r0 = m0 + gid, r1 = r0 + 8;
            int t00 = col - r0, t10 = col - r1;
            if ((unsigned)t00 < 64u)       Srel[r0 * QSTR + t00]     = sacc[j][0];
            if ((unsigned)(t00 + 1) < 64u) Srel[r0 * QSTR + t00 + 1] = sacc[j][1];
            if ((unsigned)t10 < 64u)       Srel[r1 * QSTR + t10]     = sacc[j][2];
            if ((unsigned)(t10 + 1) < 64u) Srel[r1 * QSTR + t10 + 1] = sacc[j][3];
        }
#pragma unroll
        for (int j = 0; j < 4; j++) {
            int col = np0 + 8 * j + 2 * tig;
            Spe[(m0 + gid) * QSTR + col]     = pacc[j][0];
            Spe[(m0 + gid) * QSTR + col + 1] = pacc[j][1];
            Spe[(m0 + gid + 8) * QSTR + col]     = pacc[j][2];
            Spe[(m0 + gid + 8) * QSTR + col + 1] = pacc[j][3];
        }
        __syncthreads();

        // ---- online softmax (scores already carry SCALE via Q)
        {
            float s[16];
            float mloc = -1e30f;
#pragma unroll
            for (int e = 0; e < 16; e++) {
                s[e] = Srel[srow * QSTR + tbase + e] + Spe[srow * QSTR + tbase + e];
                mloc = fmaxf(mloc, s[e]);
            }
            mloc = fmaxf(mloc, __shfl_xor_sync(0xFFFFFFFFu, mloc, 1));
            mloc = fmaxf(mloc, __shfl_xor_sync(0xFFFFFFFFu, mloc, 2));
            float m_new = fmaxf(m_run, mloc);
            float corr  = __expf(m_run - m_new);
            l_run *= corr;
            float p[16], psum = 0.f;
#pragma unroll
            for (int e = 0; e < 16; e++) { p[e] = __expf(s[e] - m_new); psum += p[e]; }
            psum += __shfl_xor_sync(0xFFFFFFFFu, psum, 1);
            psum += __shfl_xor_sync(0xFFFFFFFFu, psum, 2);
            l_run += psum;
            m_run = m_new;
            if (tg4 == 0) corr_s[srow] = corr;

            // masked P into skewed, k-PERMUTED plane + zero complement
#pragma unroll
            for (int e = 0; e < 16; e++) {
                int t = tbase + e;
                float jj = (float)(jc + t);
                float mk = fminf(1.f, fmaxf(0.f, (jj - 1023.f + spanL) * (1.f / 32.f) + 1.f));
                float pm = to_tf32(p[e] * mk);
                int u  = srow + t;
                Ps[srow * PSTR2 + perm8(u)] = pm;
                int uz = (t < srow) ? t : t + 64;
                Ps[srow * PSTR2 + perm8(uz)] = 0.f;
            }
        }
        __syncthreads();

        // ---- AV: oacc = oacc*corr + P_abs @ V^T  (LDS.64 frags)
        {
            float cA = corr_s[m0 + gid], cB = corr_s[m0 + gid + 8];
#pragma unroll
            for (int j = 0; j < 4; j++) {
                oacc[j][0] *= cA; oacc[j][1] *= cA;
                oacc[j][2] *= cB; oacc[j][3] *= cB;
            }
#pragma unroll
            for (int k0 = 0; k0 < 128; k0 += 8) {
                float2 pa = *(const float2*)&Ps[(m0 + gid) * PSTR2 + k0 + 2 * tig];
                float2 pb = *(const float2*)&Ps[(m0 + gid + 8) * PSTR2 + k0 + 2 * tig];
                uint32_t a0 = __float_as_uint(pa.x), a2 = __float_as_uint(pa.y);
                uint32_t a1 = __float_as_uint(pb.x), a3 = __float_as_uint(pb.y);
#pragma unroll
                for (int j = 0; j < 4; j++) {
                    float2 vb = *(const float2*)&Vs[(np0 + 8 * j + gid) * VSTR + k0 + 2 * tig];
                    MMA_TF32(oacc[j], a0, a1, a2, a3,
                             __float_as_uint(vb.x), __float_as_uint(vb.y));
                }
            }
        }
    }

    __syncthreads();
    if (tg4 == 0) linv_s[srow] = 1.f / l_run;
    __syncthreads();

    // epilogue: g_ctx[b][i0+row][kh][d]
    {
        float lA = linv_s[m0 + gid], lB = linv_s[m0 + gid + 8];
        int b = bk >> 3;
        int r0 = i0 + m0 + gid;
#pragma unroll
        for (int j = 0; j < 4; j++) {
            int col = np0 + 8 * j + 2 * tig;
            float* p0 = g_ctx + ((size_t)(b * Mm + r0) * Kk + kh) * Dd + col;
            float* p1 = g_ctx + ((size_t)(b * Mm + r0 + 8) * Kk + kh) * Dd + col;
            *(float2*)p0 = make_float2(oacc[j][0] * lA, oacc[j][1] * lA);
            *(float2*)p1 = make_float2(oacc[j][2] * lB, oacc[j][3] * lB);
        }
    }
}

// ---------------------------------------------------------------------------
extern "C" void kernel_launch(void* const* d_in, const int* in_sizes, int n_in,
                              void* d_out, int out_size) {
    const float* query = (const float*)d_in[0];
    const float* key   = (const float*)d_in[1];
    const float* value = (const float*)d_in[2];
    const float* pe    = (const float*)d_in[3];
    const float* Wq    = (const float*)d_in[4];
    const float* Wk    = (const float*)d_in[5];
    const float* Wv    = (const float*)d_in[6];
    const float* Wo    = (const float*)d_in[7];
    const float* span  = (const float*)d_in[8];
    float* out = (float*)d_out;

    cudaFuncSetAttribute(attn_mma_kernel,
                         cudaFuncAttributeMaxDynamicSharedMemorySize,
                         ATTN_SMEM_FLOATS * (int)sizeof(float));

    proj_qkv_kernel<<<dim3(Bb * Mm / 128, 4), 256>>>(query, Wq, Mm, 0);
    proj_qkv_kernel<<<dim3(Bb * SKk / 128, 4), 256>>>(key, Wk, SKk, 1);
    proj_qkv_kernel<<<dim3(Bb * SKk / 128, 4), 256>>>(value, Wv, SKk, 2);
    pe_prep_kernel<<<(Ll * Dd + 255) / 256, 256>>>(pe);

    attn_mma_kernel<<<dim3(Mm / 64, BKC), 256,
                      ATTN_SMEM_FLOATS * (int)sizeof(float)>>>(span);

    proj_out_kernel<<<dim3(Bb * Mm / 128, 4), 256>>>(Wo, out);
}

// round 8
// speedup vs baseline: 1.4345x; 1.1637x over previous
#include <cuda_runtime.h>
#include <cuda_bf16.h>
#include <cstdint>

// Problem constants
#define Bb   8
#define Mm   512
#define Ll   1024
#define Hh   512
#define Kk   8
#define Dd   64
#define SKk  1536           // M + L
#define BKC  64             // B * K
#define SCALE 0.125f

// Scratch (device globals)
__device__ float gq[(size_t)BKC * Mm * Dd];      // [bk][s][d]
__device__ float gk[(size_t)BKC * SKk * Dd];     // [bk][s][d]
__device__ float gv[(size_t)BKC * Dd * SKk];     // [bk][d][s]  (transposed)
__device__ float gpe[Ll * Dd];                   // [j][d]
__device__ float g_ctx[(size_t)Bb * Mm * Hh];    // [B, M, K, D]

__device__ __forceinline__ float to_tf32(float x) {
    uint32_t r;
    asm("cvt.rna.tf32.f32 %0, %1;" : "=r"(r) : "f"(x));
    return __uint_as_float(r);
}
__device__ __forceinline__ uint32_t rna_u(float x) {
    uint32_t r;
    asm("cvt.rna.tf32.f32 %0, %1;" : "=r"(r) : "f"(x));
    return r;
}

#define MMA_TF32(c, a0, a1, a2, a3, b0, b1)                                   \
    asm volatile(                                                             \
        "mma.sync.aligned.m16n8k8.row.col.f32.tf32.tf32.f32 "                 \
        "{%0,%1,%2,%3},{%4,%5,%6,%7},{%8,%9},{%0,%1,%2,%3};"                  \
        : "+f"(c[0]), "+f"(c[1]), "+f"(c[2]), "+f"(c[3])                      \
        : "r"(a0), "r"(a1), "r"(a2), "r"(a3), "r"(b0), "r"(b1));

#define PJSTR 36

// ---------------------------------------------------------------------------
// Single-pass tf32 QKV projection GEMM: Y = X @ W^T, head-split stores.
// ---------------------------------------------------------------------------
__global__ __launch_bounds__(256) void proj_qkv_kernel(
        const float* __restrict__ X, const float* __restrict__ W,
        int S, int sel) {
    __shared__ float Xs[128 * PJSTR];
    __shared__ float Ws[128 * PJSTR];

    const int tid  = threadIdx.x;
    const int lane = tid & 31;
    const int wid  = tid >> 5;
    const int warp_m = wid >> 1;
    const int warp_n = wid & 1;
    const int gid = lane >> 2;
    const int tig = lane & 3;
    const int row0 = blockIdx.x * 128;
    const int col0 = blockIdx.y * 128;

    float c[2][8][4];
#pragma unroll
    for (int f = 0; f < 2; f++)
#pragma unroll
        for (int j = 0; j < 8; j++)
#pragma unroll
            for (int t = 0; t < 4; t++) c[f][j][t] = 0.f;

    for (int k0 = 0; k0 < 512; k0 += 32) {
#pragma unroll
        for (int i = 0; i < 4; i++) {
            int f4 = tid + i * 256;
            int r  = f4 >> 3;
            int kq = (f4 & 7) << 2;
            float4 xv = *(const float4*)(X + (size_t)(row0 + r) * 512 + k0 + kq);
            *(float4*)&Xs[r * PJSTR + kq] = xv;
            float4 wv = *(const float4*)(W + (size_t)(col0 + r) * 512 + k0 + kq);
            *(float4*)&Ws[r * PJSTR + kq] = wv;
        }
        __syncthreads();

#pragma unroll
        for (int kk = 0; kk < 32; kk += 8) {
            uint32_t a[2][4];
#pragma unroll
            for (int f = 0; f < 2; f++) {
                int rbase = warp_m * 32 + f * 16 + gid;
#pragma unroll
                for (int rg = 0; rg < 4; rg++) {
                    int r    = rbase + ((rg & 1) << 3);
                    int kcol = kk + tig + ((rg >> 1) << 2);
                    a[f][rg] = rna_u(Xs[r * PJSTR + kcol]);
                }
            }
#pragma unroll
            for (int j = 0; j < 8; j++) {
                int cidx = warp_n * 64 + j * 8 + gid;
                uint32_t b0 = rna_u(Ws[cidx * PJSTR + kk + tig]);
                uint32_t b1 = rna_u(Ws[cidx * PJSTR + kk + tig + 4]);
#pragma unroll
                for (int f = 0; f < 2; f++)
                    MMA_TF32(c[f][j], a[f][0], a[f][1], a[f][2], a[f][3], b0, b1);
            }
        }
        __syncthreads();
    }

#pragma unroll
    for (int f = 0; f < 2; f++) {
        int rloc = warp_m * 32 + f * 16 + gid;
#pragma unroll
        for (int j = 0; j < 8; j++) {
            int cc = col0 + warp_n * 64 + j * 8 + 2 * tig;
#pragma unroll
            for (int h = 0; h < 2; h++) {
                int r = row0 + rloc + h * 8;
                int b = r / S, s = r - b * S;
                int kh = cc >> 6, d = cc & 63;
                int bk = b * Kk + kh;
                float tx = to_tf32(c[f][j][h * 2]);
                float ty = to_tf32(c[f][j][h * 2 + 1]);
                if (sel == 0) {
                    *(float2*)&gq[((size_t)bk * Mm + s) * Dd + d] = make_float2(tx, ty);
                } else if (sel == 1) {
                    *(float2*)&gk[((size_t)bk * SKk + s) * Dd + d] = make_float2(tx, ty);
                } else {
                    gv[((size_t)bk * Dd + d) * SKk + s]     = tx;
                    gv[((size_t)bk * Dd + d + 1) * SKk + s] = ty;
                }
            }
        }
    }
}

// ---------------------------------------------------------------------------
// 3-pass split-tf32 output GEMM: out = g_ctx @ Wo^T  (precision anchor)
// ---------------------------------------------------------------------------
__global__ __launch_bounds__(256) void proj_out_kernel(
        const float* __restrict__ W, float* __restrict__ Yout) {
    __shared__ float Xs[128 * PJSTR];
    __shared__ float Ws[128 * PJSTR];

    const int tid  = threadIdx.x;
    const int lane = tid & 31;
    const int wid  = tid >> 5;
    const int warp_m = wid >> 1;
    const int warp_n = wid & 1;
    const int gid = lane >> 2;
    const int tig = lane & 3;
    const int row0 = blockIdx.x * 128;
    const int col0 = blockIdx.y * 128;

    float c[2][8][4];
#pragma unroll
    for (int f = 0; f < 2; f++)
#pragma unroll
        for (int j = 0; j < 8; j++)
#pragma unroll
            for (int t = 0; t < 4; t++) c[f][j][t] = 0.f;

    for (int k0 = 0; k0 < 512; k0 += 32) {
#pragma unroll
        for (int i = 0; i < 4; i++) {
            int f4 = tid + i * 256;
            int r  = f4 >> 3;
            int kq = (f4 & 7) << 2;
            float4 xv = *(const float4*)(g_ctx + (size_t)(row0 + r) * 512 + k0 + kq);
            *(float4*)&Xs[r * PJSTR + kq] = xv;
            float4 wv = *(const float4*)(W + (size_t)(col0 + r) * 512 + k0 + kq);
            *(float4*)&Ws[r * PJSTR + kq] = wv;
        }
        __syncthreads();

#pragma unroll
        for (int kk = 0; kk < 32; kk += 8) {
            uint32_t ahi[2][4], alo[2][4];
#pragma unroll
            for (int f = 0; f < 2; f++) {
                int rbase = warp_m * 32 + f * 16 + gid;
#pragma unroll
                for (int rg = 0; rg < 4; rg++) {
                    int r    = rbase + ((rg & 1) << 3);
                    int kcol = kk + tig + ((rg >> 1) << 2);
                    float x  = Xs[r * PJSTR + kcol];
                    uint32_t hb = __float_as_uint(x) & 0xFFFFE000u;
                    ahi[f][rg] = hb;
                    alo[f][rg] = __float_as_uint(x - __uint_as_float(hb));
                }
            }
#pragma unroll
            for (int j = 0; j < 8; j++) {
                int cidx = warp_n * 64 + j * 8 + gid;
                float b0f = Ws[cidx * PJSTR + kk + tig];
                float b1f = Ws[cidx * PJSTR + kk + tig + 4];
                uint32_t b0h = __float_as_uint(b0f) & 0xFFFFE000u;
                uint32_t b1h = __float_as_uint(b1f) & 0xFFFFE000u;
                uint32_t b0l = __float_as_uint(b0f - __uint_as_float(b0h));
                uint32_t b1l = __float_as_uint(b1f - __uint_as_float(b1h));
#pragma unroll
                for (int f = 0; f < 2; f++) {
                    MMA_TF32(c[f][j], ahi[f][0], ahi[f][1], ahi[f][2], ahi[f][3], b0h, b1h);
                    MMA_TF32(c[f][j], ahi[f][0], ahi[f][1], ahi[f][2], ahi[f][3], b0l, b1l);
                    MMA_TF32(c[f][j], alo[f][0], alo[f][1], alo[f][2], alo[f][3], b0h, b1h);
                }
            }
        }
        __syncthreads();
    }

#pragma unroll
    for (int f = 0; f < 2; f++) {
        int rloc = warp_m * 32 + f * 16 + gid;
#pragma unroll
        for (int j = 0; j < 8; j++) {
            int cc = col0 + warp_n * 64 + j * 8 + 2 * tig;
#pragma unroll
            for (int h = 0; h < 2; h++) {
                int r = row0 + rloc + h * 8;
                *(float2*)(Yout + (size_t)r * 512 + cc) =
                    make_float2(c[f][j][h * 2], c[f][j][h * 2 + 1]);
            }
        }
    }
}

// ---------------------------------------------------------------------------
// PE transpose prep: gpe[j][d] = tf32(pe[d][j])
// ---------------------------------------------------------------------------
__global__ void pe_prep_kernel(const float* __restrict__ pe) {
    int idx = blockIdx.x * 256 + threadIdx.x;
    if (idx < Ll * Dd) {
        int j = idx >> 6, d = idx & 63;
        gpe[idx] = to_tf32(pe[d * Ll + j]);
    }
}

// ---------------------------------------------------------------------------
// Single-pass tf32 MMA banded attention (round-5 structure, 1 CTA/SM)
// + SCALE folded into Q load (bit-identical)
// + banded j-skip: warp (mb, nh) only computes QK n-tiles intersecting the
//   band t = col - row in [0, 64). nh=0: j in [2*mb, 8); nh=1: j in [0, 2*mb+2).
//   Per-SMSP warp pairs sum to 10 tiles -> balanced. 512 -> 320 QK MMAs/chunk.
// ---------------------------------------------------------------------------
#define QSTR 68
#define KSTR 68
#define VSTR 132
#define PSTR2 132
#define OFF_Q    0
#define OFF_K    (OFF_Q + 64 * QSTR)
#define OFF_V    (OFF_K + 128 * KSTR)
#define OFF_PE   (OFF_V + 64 * VSTR)
#define OFF_SREL (OFF_PE + 64 * QSTR)
#define OFF_SPE  (OFF_SREL + 64 * QSTR)
#define OFF_CORR (OFF_SPE + 64 * QSTR)
#define OFF_LINV (OFF_CORR + 64)
#define ATTN_SMEM_FLOATS (OFF_LINV + 64)
#define OFF_P    OFF_K

__global__ __launch_bounds__(256) void attn_mma_kernel(
        const float* __restrict__ span_val) {
    extern __shared__ float sm[];
    float* Qs   = sm + OFF_Q;
    float* Ks   = sm + OFF_K;
    float* Vs   = sm + OFF_V;
    float* PEs  = sm + OFF_PE;
    float* Srel = sm + OFF_SREL;
    float* Spe  = sm + OFF_SPE;
    float* corr_s = sm + OFF_CORR;
    float* linv_s = sm + OFF_LINV;
    float* Ps   = sm + OFF_P;

    const uint32_t* Qu  = (const uint32_t*)Qs;
    const uint32_t* Ku  = (const uint32_t*)Ks;
    const uint32_t* Vu  = (const uint32_t*)Vs;
    const uint32_t* PEu = (const uint32_t*)PEs;
    const uint32_t* Pu  = (const uint32_t*)Ps;

    const int tid  = threadIdx.x;
    const int lane = tid & 31;
    const int wid  = tid >> 5;
    const int gid  = lane >> 2;
    const int tig  = lane & 3;
    const int bk   = blockIdx.y;
    const int i0   = blockIdx.x * 64;
    const int kh   = bk & 7;

    const int mb  = wid & 3;
    const int nh  = wid >> 2;
    const int m0  = mb * 16;
    const int nq0 = nh * 64;
    const int np0 = nh * 32;
    // banded j-range for QK n-tiles
    const int jlo = (nh == 0) ? 2 * mb : 0;
    const int jhi = (nh == 0) ? 8 : 2 * mb + 2;

    const int srow = tid >> 2;
    const int tg4  = tid & 3;
    const int tbase = tg4 * 16;
    const float spanL = span_val[kh] * 1024.f;

    // Q tile (pre-scaled by SCALE; exact power of two — bit-identical scores)
    {
        const float* gqp = gq + ((size_t)bk * Mm + i0) * Dd;
#pragma unroll
        for (int it = 0; it < 4; it++) {
            int idx = tid + it * 256;
            int r = idx >> 4, c4 = (idx & 15) << 2;
            float4 v = *(const float4*)(gqp + (size_t)r * Dd + c4);
            v.x *= SCALE; v.y *= SCALE; v.z *= SCALE; v.w *= SCALE;
            *(float4*)&Qs[r * QSTR + c4] = v;
        }
    }

    float oacc[4][4];
#pragma unroll
    for (int j = 0; j < 4; j++)
#pragma unroll
        for (int t = 0; t < 4; t++) oacc[j][t] = 0.f;

    float m_run = -1e30f, l_run = 0.f;

    for (int jc = 0; jc < Ll; jc += 64) {
        __syncthreads();
        {
            const float* gkp = gk + ((size_t)bk * SKk + i0 + jc) * Dd;
#pragma unroll
            for (int it = 0; it < 8; it++) {
                int idx = tid + it * 256;
                int r = idx >> 4, c4 = (idx & 15) << 2;
                *(float4*)&Ks[r * KSTR + c4] = *(const float4*)(gkp + (size_t)r * Dd + c4);
            }
            const float* gvp = gv + (size_t)bk * Dd * SKk + i0 + jc;
#pragma unroll
            for (int it = 0; it < 8; it++) {
                int idx = tid + it * 256;
                int d = idx >> 5, c4 = (idx & 31) << 2;
                *(float4*)&Vs[d * VSTR + c4] = *(const float4*)(gvp + (size_t)d * SKk + c4);
            }
            const float* gpp = gpe + (size_t)jc * Dd;
#pragma unroll
            for (int it = 0; it < 4; it++) {
                int idx = tid + it * 256;
                int r = idx >> 4, c4 = (idx & 15) << 2;
                *(float4*)&PEs[r * QSTR + c4] = *(const float4*)(gpp + (size_t)r * Dd + c4);
            }
        }
        __syncthreads();

        // ---- QK^T band tiles + Q@PE (64x64), single-pass tf32
        float sacc[8][4], pacc[4][4];
#pragma unroll
        for (int j = 0; j < 8; j++)
#pragma unroll
            for (int t = 0; t < 4; t++) sacc[j][t] = 0.f;
#pragma unroll
        for (int j = 0; j < 4; j++)
#pragma unroll
            for (int t = 0; t < 4; t++) pacc[j][t] = 0.f;

#pragma unroll
        for (int k0 = 0; k0 < 64; k0 += 8) {
            int ar = (m0 + gid) * QSTR + k0 + tig;
            uint32_t a0 = Qu[ar];
            uint32_t a1 = Qu[ar + 8 * QSTR];
            uint32_t a2 = Qu[ar + 4];
            uint32_t a3 = Qu[ar + 8 * QSTR + 4];
#pragma unroll
            for (int j = 0; j < 8; j++) {
                if (j >= jlo && j < jhi) {
                    int br = (nq0 + 8 * j + gid) * KSTR + k0 + tig;
                    MMA_TF32(sacc[j], a0, a1, a2, a3, Ku[br], Ku[br + 4]);
                }
            }
#pragma unroll
            for (int j = 0; j < 4; j++) {
                int br = (np0 + 8 * j + gid) * QSTR + k0 + tig;
                MMA_TF32(pacc[j], a0, a1, a2, a3, PEu[br], PEu[br + 4]);
            }
        }

        // scatter QK band -> de-skewed Srel[i][col-row]
#pragma unroll
        for (int j = 0; j < 8; j++) {
            if (j >= jlo && j < jhi) {
                int col = nq0 + 8 * j + 2 * tig;
                int r0 = m0 + gid, r1 = r0 + 8;
                int t00 = col - r0, t10 = col - r1;
                if ((unsigned)t00 < 64u)       Srel[r0 * QSTR + t00]     = sacc[j][0];
                if ((unsigned)(t00 + 1) < 64u) Srel[r0 * QSTR + t00 + 1] = sacc[j][1];
                if ((unsigned)t10 < 64u)       Srel[r1 * QSTR + t10]     = sacc[j][2];
                if ((unsigned)(t10 + 1) < 64u) Srel[r1 * QSTR + t10 + 1] = sacc[j][3];
            }
        }
#pragma unroll
        for (int j = 0; j < 4; j++) {
            int col = np0 + 8 * j + 2 * tig;
            Spe[(m0 + gid) * QSTR + col]     = pacc[j][0];
            Spe[(m0 + gid) * QSTR + col + 1] = pacc[j][1];
            Spe[(m0 + gid + 8) * QSTR + col]     = pacc[j][2];
            Spe[(m0 + gid + 8) * QSTR + col + 1] = pacc[j][3];
        }
        __syncthreads();

        // ---- online softmax (scores already carry SCALE via Q)
        {
            float s[16];
            float mloc = -1e30f;
#pragma unroll
            for (int e = 0; e < 16; e++) {
                s[e] = Srel[srow * QSTR + tbase + e] + Spe[srow * QSTR + tbase + e];
                mloc = fmaxf(mloc, s[e]);
            }
            mloc = fmaxf(mloc, __shfl_xor_sync(0xFFFFFFFFu, mloc, 1));
            mloc = fmaxf(mloc, __shfl_xor_sync(0xFFFFFFFFu, mloc, 2));
            float m_new = fmaxf(m_run, mloc);
            float corr  = __expf(m_run - m_new);
            l_run *= corr;
            float p[16], psum = 0.f;
#pragma unroll
            for (int e = 0; e < 16; e++) { p[e] = __expf(s[e] - m_new); psum += p[e]; }
            psum += __shfl_xor_sync(0xFFFFFFFFu, psum, 1);
            psum += __shfl_xor_sync(0xFFFFFFFFu, psum, 2);
            l_run += psum;
            m_run = m_new;
            if (tg4 == 0) corr_s[srow] = corr;

            // masked P into skewed plane + zero complement
#pragma unroll
            for (int e = 0; e < 16; e++) {
                int t = tbase + e;
                float jj = (float)(jc + t);
                float mk = fminf(1.f, fmaxf(0.f, (jj - 1023.f + spanL) * (1.f / 32.f) + 1.f));
                float pm = to_tf32(p[e] * mk);
                int u = srow + t;
                Ps[srow * PSTR2 + u] = pm;
                int uz = (t < srow) ? t : t + 64;
                Ps[srow * PSTR2 + uz] = 0.f;
            }
        }
        __syncthreads();

        // ---- AV: oacc = oacc*corr + P_abs @ V^T
        {
            float cA = corr_s[m0 + gid], cB = corr_s[m0 + gid + 8];
#pragma unroll
            for (int j = 0; j < 4; j++) {
                oacc[j][0] *= cA; oacc[j][1] *= cA;
                oacc[j][2] *= cB; oacc[j][3] *= cB;
            }
#pragma unroll
            for (int k0 = 0; k0 < 128; k0 += 8) {
                int ar = (m0 + gid) * PSTR2 + k0 + tig;
                uint32_t a0 = Pu[ar];
                uint32_t a1 = Pu[ar + 8 * PSTR2];
                uint32_t a2 = Pu[ar + 4];
                uint32_t a3 = Pu[ar + 8 * PSTR2 + 4];
#pragma unroll
                for (int j = 0; j < 4; j++) {
                    int br = (np0 + 8 * j + gid) * VSTR + k0 + tig;
                    MMA_TF32(oacc[j], a0, a1, a2, a3, Vu[br], Vu[br + 4]);
                }
            }
        }
    }

    __syncthreads();
    if (tg4 == 0) linv_s[srow] = 1.f / l_run;
    __syncthreads();

    // epilogue: g_ctx[b][i0+row][kh][d]
    {
        float lA = linv_s[m0 + gid], lB = linv_s[m0 + gid + 8];
        int b = bk >> 3;
        int r0 = i0 + m0 + gid;
#pragma unroll
        for (int j = 0; j < 4; j++) {
            int col = np0 + 8 * j + 2 * tig;
            float* p0 = g_ctx + ((size_t)(b * Mm + r0) * Kk + kh) * Dd + col;
            float* p1 = g_ctx + ((size_t)(b * Mm + r0 + 8) * Kk + kh) * Dd + col;
            *(float2*)p0 = make_float2(oacc[j][0] * lA, oacc[j][1] * lA);
            *(float2*)p1 = make_float2(oacc[j][2] * lB, oacc[j][3] * lB);
        }
    }
}

// ---------------------------------------------------------------------------
extern "C" void kernel_launch(void* const* d_in, const int* in_sizes, int n_in,
                              void* d_out, int out_size) {
    const float* query = (const float*)d_in[0];
    const float* key   = (const float*)d_in[1];
    const float* value = (const float*)d_in[2];
    const float* pe    = (const float*)d_in[3];
    const float* Wq    = (const float*)d_in[4];
    const float* Wk    = (const float*)d_in[5];
    const float* Wv    = (const float*)d_in[6];
    const float* Wo    = (const float*)d_in[7];
    const float* span  = (const float*)d_in[8];
    float* out = (float*)d_out;

    cudaFuncSetAttribute(attn_mma_kernel,
                         cudaFuncAttributeMaxDynamicSharedMemorySize,
                         ATTN_SMEM_FLOATS * (int)sizeof(float));

    proj_qkv_kernel<<<dim3(Bb * Mm / 128, 4), 256>>>(query, Wq, Mm, 0);
    proj_qkv_kernel<<<dim3(Bb * SKk / 128, 4), 256>>>(key, Wk, SKk, 1);
    proj_qkv_kernel<<<dim3(Bb * SKk / 128, 4), 256>>>(value, Wv, SKk, 2);
    pe_prep_kernel<<<(Ll * Dd + 255) / 256, 256>>>(pe);

    attn_mma_kernel<<<dim3(Mm / 64, BKC), 256,
                      ATTN_SMEM_FLOATS * (int)sizeof(float)>>>(span);

    proj_out_kernel<<<dim3(Bb * Mm / 128, 4), 256>>>(Wo, out);
}

// round 9
// speedup vs baseline: 1.5462x; 1.0778x over previous
#include <cuda_runtime.h>
#include <cuda_bf16.h>
#include <cstdint>

// Problem constants
#define Bb   8
#define Mm   512
#define Ll   1024
#define Hh   512
#define Kk   8
#define Dd   64
#define SKk  1536           // M + L
#define BKC  64             // B * K
#define SCALE 0.125f

// Scratch (device globals)
__device__ float gq[(size_t)BKC * Mm * Dd];      // [bk][s][d]
__device__ float gk[(size_t)BKC * SKk * Dd];     // [bk][s][d]
__device__ float gv[(size_t)BKC * Dd * SKk];     // [bk][d][s]  (transposed)
__device__ float gpe[Ll * Dd];                   // [j][d]
__device__ float g_ctx[(size_t)Bb * Mm * Hh];    // [B, M, K, D]

__device__ __forceinline__ float to_tf32(float x) {
    uint32_t r;
    asm("cvt.rna.tf32.f32 %0, %1;" : "=r"(r) : "f"(x));
    return __uint_as_float(r);
}
__device__ __forceinline__ uint32_t rna_u(float x) {
    uint32_t r;
    asm("cvt.rna.tf32.f32 %0, %1;" : "=r"(r) : "f"(x));
    return r;
}

#define MMA_TF32(c, a0, a1, a2, a3, b0, b1)                                   \
    asm volatile(                                                             \
        "mma.sync.aligned.m16n8k8.row.col.f32.tf32.tf32.f32 "                 \
        "{%0,%1,%2,%3},{%4,%5,%6,%7},{%8,%9},{%0,%1,%2,%3};"                  \
        : "+f"(c[0]), "+f"(c[1]), "+f"(c[2]), "+f"(c[3])                      \
        : "r"(a0), "r"(a1), "r"(a2), "r"(a3), "r"(b0), "r"(b1));

#define PJSTR 36

// ---------------------------------------------------------------------------
// Single-pass tf32 QKV projection GEMM: Y = X @ W^T, head-split stores.
// ---------------------------------------------------------------------------
__global__ __launch_bounds__(256) void proj_qkv_kernel(
        const float* __restrict__ X, const float* __restrict__ W,
        int S, int sel) {
    __shared__ float Xs[128 * PJSTR];
    __shared__ float Ws[128 * PJSTR];

    const int tid  = threadIdx.x;
    const int lane = tid & 31;
    const int wid  = tid >> 5;
    const int warp_m = wid >> 1;
    const int warp_n = wid & 1;
    const int gid = lane >> 2;
    const int tig = lane & 3;
    const int row0 = blockIdx.x * 128;
    const int col0 = blockIdx.y * 128;

    float c[2][8][4];
#pragma unroll
    for (int f = 0; f < 2; f++)
#pragma unroll
        for (int j = 0; j < 8; j++)
#pragma unroll
            for (int t = 0; t < 4; t++) c[f][j][t] = 0.f;

    for (int k0 = 0; k0 < 512; k0 += 32) {
#pragma unroll
        for (int i = 0; i < 4; i++) {
            int f4 = tid + i * 256;
            int r  = f4 >> 3;
            int kq = (f4 & 7) << 2;
            float4 xv = *(const float4*)(X + (size_t)(row0 + r) * 512 + k0 + kq);
            *(float4*)&Xs[r * PJSTR + kq] = xv;
            float4 wv = *(const float4*)(W + (size_t)(col0 + r) * 512 + k0 + kq);
            *(float4*)&Ws[r * PJSTR + kq] = wv;
        }
        __syncthreads();

#pragma unroll
        for (int kk = 0; kk < 32; kk += 8) {
            uint32_t a[2][4];
#pragma unroll
            for (int f = 0; f < 2; f++) {
                int rbase = warp_m * 32 + f * 16 + gid;
#pragma unroll
                for (int rg = 0; rg < 4; rg++) {
                    int r    = rbase + ((rg & 1) << 3);
                    int kcol = kk + tig + ((rg >> 1) << 2);
                    a[f][rg] = rna_u(Xs[r * PJSTR + kcol]);
                }
            }
#pragma unroll
            for (int j = 0; j < 8; j++) {
                int cidx = warp_n * 64 + j * 8 + gid;
                uint32_t b0 = rna_u(Ws[cidx * PJSTR + kk + tig]);
                uint32_t b1 = rna_u(Ws[cidx * PJSTR + kk + tig + 4]);
#pragma unroll
                for (int f = 0; f < 2; f++)
                    MMA_TF32(c[f][j], a[f][0], a[f][1], a[f][2], a[f][3], b0, b1);
            }
        }
        __syncthreads();
    }

#pragma unroll
    for (int f = 0; f < 2; f++) {
        int rloc = warp_m * 32 + f * 16 + gid;
#pragma unroll
        for (int j = 0; j < 8; j++) {
            int cc = col0 + warp_n * 64 + j * 8 + 2 * tig;
#pragma unroll
            for (int h = 0; h < 2; h++) {
                int r = row0 + rloc + h * 8;
                int b = r / S, s = r - b * S;
                int kh = cc >> 6, d = cc & 63;
                int bk = b * Kk + kh;
                float tx = to_tf32(c[f][j][h * 2]);
                float ty = to_tf32(c[f][j][h * 2 + 1]);
                if (sel == 0) {
                    *(float2*)&gq[((size_t)bk * Mm + s) * Dd + d] = make_float2(tx, ty);
                } else if (sel == 1) {
                    *(float2*)&gk[((size_t)bk * SKk + s) * Dd + d] = make_float2(tx, ty);
                } else {
                    gv[((size_t)bk * Dd + d) * SKk + s]     = tx;
                    gv[((size_t)bk * Dd + d + 1) * SKk + s] = ty;
                }
            }
        }
    }
}

// ---------------------------------------------------------------------------
// 3-pass split-tf32 output GEMM: out = g_ctx @ Wo^T  (precision anchor)
// ---------------------------------------------------------------------------
__global__ __launch_bounds__(256) void proj_out_kernel(
        const float* __restrict__ W, float* __restrict__ Yout) {
    __shared__ float Xs[128 * PJSTR];
    __shared__ float Ws[128 * PJSTR];

    const int tid  = threadIdx.x;
    const int lane = tid & 31;
    const int wid  = tid >> 5;
    const int warp_m = wid >> 1;
    const int warp_n = wid & 1;
    const int gid = lane >> 2;
    const int tig = lane & 3;
    const int row0 = blockIdx.x * 128;
    const int col0 = blockIdx.y * 128;

    float c[2][8][4];
#pragma unroll
    for (int f = 0; f < 2; f++)
#pragma unroll
        for (int j = 0; j < 8; j++)
#pragma unroll
            for (int t = 0; t < 4; t++) c[f][j][t] = 0.f;

    for (int k0 = 0; k0 < 512; k0 += 32) {
#pragma unroll
        for (int i = 0; i < 4; i++) {
            int f4 = tid + i * 256;
            int r  = f4 >> 3;
            int kq = (f4 & 7) << 2;
            float4 xv = *(const float4*)(g_ctx + (size_t)(row0 + r) * 512 + k0 + kq);
            *(float4*)&Xs[r * PJSTR + kq] = xv;
            float4 wv = *(const float4*)(W + (size_t)(col0 + r) * 512 + k0 + kq);
            *(float4*)&Ws[r * PJSTR + kq] = wv;
        }
        __syncthreads();

#pragma unroll
        for (int kk = 0; kk < 32; kk += 8) {
            uint32_t ahi[2][4], alo[2][4];
#pragma unroll
            for (int f = 0; f < 2; f++) {
                int rbase = warp_m * 32 + f * 16 + gid;
#pragma unroll
                for (int rg = 0; rg < 4; rg++) {
                    int r    = rbase + ((rg & 1) << 3);
                    int kcol = kk + tig + ((rg >> 1) << 2);
                    float x  = Xs[r * PJSTR + kcol];
                    uint32_t hb = __float_as_uint(x) & 0xFFFFE000u;
                    ahi[f][rg] = hb;
                    alo[f][rg] = __float_as_uint(x - __uint_as_float(hb));
                }
            }
#pragma unroll
            for (int j = 0; j < 8; j++) {
                int cidx = warp_n * 64 + j * 8 + gid;
                float b0f = Ws[cidx * PJSTR + kk + tig];
                float b1f = Ws[cidx * PJSTR + kk + tig + 4];
                uint32_t b0h = __float_as_uint(b0f) & 0xFFFFE000u;
                uint32_t b1h = __float_as_uint(b1f) & 0xFFFFE000u;
                uint32_t b0l = __float_as_uint(b0f - __uint_as_float(b0h));
                uint32_t b1l = __float_as_uint(b1f - __uint_as_float(b1h));
#pragma unroll
                for (int f = 0; f < 2; f++) {
                    MMA_TF32(c[f][j], ahi[f][0], ahi[f][1], ahi[f][2], ahi[f][3], b0h, b1h);
                    MMA_TF32(c[f][j], ahi[f][0], ahi[f][1], ahi[f][2], ahi[f][3], b0l, b1l);
                    MMA_TF32(c[f][j], alo[f][0], alo[f][1], alo[f][2], alo[f][3], b0h, b1h);
                }
            }
        }
        __syncthreads();
    }

#pragma unroll
    for (int f = 0; f < 2; f++) {
        int rloc = warp_m * 32 + f * 16 + gid;
#pragma unroll
        for (int j = 0; j < 8; j++) {
            int cc = col0 + warp_n * 64 + j * 8 + 2 * tig;
#pragma unroll
            for (int h = 0; h < 2; h++) {
                int r = row0 + rloc + h * 8;
                *(float2*)(Yout + (size_t)r * 512 + cc) =
                    make_float2(c[f][j][h * 2], c[f][j][h * 2 + 1]);
            }
        }
    }
}

// ---------------------------------------------------------------------------
// PE transpose prep: gpe[j][d] = tf32(pe[d][j])
// ---------------------------------------------------------------------------
__global__ void pe_prep_kernel(const float* __restrict__ pe) {
    int idx = blockIdx.x * 256 + threadIdx.x;
    if (idx < Ll * Dd) {
        int j = idx >> 6, d = idx & 63;
        gpe[idx] = to_tf32(pe[d * Ll + j]);
    }
}

// ---------------------------------------------------------------------------
// Single-pass tf32 MMA banded attention.
// Per-warp BALANCED band tiles:
//   row-block mb = wid&3 (rows 16*mb..+15); in-band QK 8-col tiles are
//   jt in [2mb, 2mb+9] (10 tiles); warp pair (nh=0/1) splits 5/5.
//   AV contraction skips k-blocks outside [2mb, 2mb+9] (P is zero there).
// Both cuts are bit-identical to the full computation.
// ---------------------------------------------------------------------------
#define QSTR 68
#define KSTR 68
#define VSTR 132
#define PSTR2 132
#define OFF_Q    0
#define OFF_K    (OFF_Q + 64 * QSTR)
#define OFF_V    (OFF_K + 128 * KSTR)
#define OFF_PE   (OFF_V + 64 * VSTR)
#define OFF_SREL (OFF_PE + 64 * QSTR)
#define OFF_SPE  (OFF_SREL + 64 * QSTR)
#define OFF_CORR (OFF_SPE + 64 * QSTR)
#define OFF_LINV (OFF_CORR + 64)
#define ATTN_SMEM_FLOATS (OFF_LINV + 64)
#define OFF_P    OFF_K

__global__ __launch_bounds__(256) void attn_mma_kernel(
        const float* __restrict__ span_val) {
    extern __shared__ float sm[];
    float* Qs   = sm + OFF_Q;
    float* Ks   = sm + OFF_K;
    float* Vs   = sm + OFF_V;
    float* PEs  = sm + OFF_PE;
    float* Srel = sm + OFF_SREL;
    float* Spe  = sm + OFF_SPE;
    float* corr_s = sm + OFF_CORR;
    float* linv_s = sm + OFF_LINV;
    float* Ps   = sm + OFF_P;

    const uint32_t* Qu  = (const uint32_t*)Qs;
    const uint32_t* Ku  = (const uint32_t*)Ks;
    const uint32_t* Vu  = (const uint32_t*)Vs;
    const uint32_t* PEu = (const uint32_t*)PEs;
    const uint32_t* Pu  = (const uint32_t*)Ps;

    const int tid  = threadIdx.x;
    const int lane = tid & 31;
    const int wid  = tid >> 5;
    const int gid  = lane >> 2;
    const int tig  = lane & 3;
    const int bk   = blockIdx.y;
    const int i0   = blockIdx.x * 64;
    const int kh   = bk & 7;

    const int mb  = wid & 3;
    const int nh  = wid >> 5 ? 0 : (wid >> 2);   // wid>>2 in {0,1}
    const int m0  = mb * 16;
    const int np0 = (wid >> 2) * 32;
    const int jt0 = 2 * mb + 5 * (wid >> 2);     // first of 5 owned QK tiles

    const int srow = tid >> 2;
    const int tg4  = tid & 3;
    const int tbase = tg4 * 16;
    const float spanL = span_val[kh] * 1024.f;

    // Q tile (pre-scaled by SCALE; exact power of two — bit-identical scores)
    {
        const float* gqp = gq + ((size_t)bk * Mm + i0) * Dd;
#pragma unroll
        for (int it = 0; it < 4; it++) {
            int idx = tid + it * 256;
            int r = idx >> 4, c4 = (idx & 15) << 2;
            float4 v = *(const float4*)(gqp + (size_t)r * Dd + c4);
            v.x *= SCALE; v.y *= SCALE; v.z *= SCALE; v.w *= SCALE;
            *(float4*)&Qs[r * QSTR + c4] = v;
        }
    }

    float oacc[4][4];
#pragma unroll
    for (int j = 0; j < 4; j++)
#pragma unroll
        for (int t = 0; t < 4; t++) oacc[j][t] = 0.f;

    float m_run = -1e30f, l_run = 0.f;

    for (int jc = 0; jc < Ll; jc += 64) {
        __syncthreads();
        {
            const float* gkp = gk + ((size_t)bk * SKk + i0 + jc) * Dd;
#pragma unroll
            for (int it = 0; it < 8; it++) {
                int idx = tid + it * 256;
                int r = idx >> 4, c4 = (idx & 15) << 2;
                *(float4*)&Ks[r * KSTR + c4] = *(const float4*)(gkp + (size_t)r * Dd + c4);
            }
            const float* gvp = gv + (size_t)bk * Dd * SKk + i0 + jc;
#pragma unroll
            for (int it = 0; it < 8; it++) {
                int idx = tid + it * 256;
                int d = idx >> 5, c4 = (idx & 31) << 2;
                *(float4*)&Vs[d * VSTR + c4] = *(const float4*)(gvp + (size_t)d * SKk + c4);
            }
            const float* gpp = gpe + (size_t)jc * Dd;
#pragma unroll
            for (int it = 0; it < 4; it++) {
                int idx = tid + it * 256;
                int r = idx >> 4, c4 = (idx & 15) << 2;
                *(float4*)&PEs[r * QSTR + c4] = *(const float4*)(gpp + (size_t)r * Dd + c4);
            }
        }
        __syncthreads();

        // ---- QK^T band tiles (5 per warp) + Q@PE (4 per warp), tf32
        float sacc[5][4], pacc[4][4];
#pragma unroll
        for (int j = 0; j < 5; j++)
#pragma unroll
            for (int t = 0; t < 4; t++) sacc[j][t] = 0.f;
#pragma unroll
        for (int j = 0; j < 4; j++)
#pragma unroll
            for (int t = 0; t < 4; t++) pacc[j][t] = 0.f;

#pragma unroll
        for (int k0 = 0; k0 < 64; k0 += 8) {
            int ar = (m0 + gid) * QSTR + k0 + tig;
            uint32_t a0 = Qu[ar];
            uint32_t a1 = Qu[ar + 8 * QSTR];
            uint32_t a2 = Qu[ar + 4];
            uint32_t a3 = Qu[ar + 8 * QSTR + 4];
#pragma unroll
            for (int jj = 0; jj < 5; jj++) {
                int br = ((jt0 + jj) * 8 + gid) * KSTR + k0 + tig;
                MMA_TF32(sacc[jj], a0, a1, a2, a3, Ku[br], Ku[br + 4]);
            }
#pragma unroll
            for (int j = 0; j < 4; j++) {
                int br = (np0 + 8 * j + gid) * QSTR + k0 + tig;
                MMA_TF32(pacc[j], a0, a1, a2, a3, PEu[br], PEu[br + 4]);
            }
        }

        // scatter QK band -> de-skewed Srel[i][col-row]
#pragma unroll
        for (int jj = 0; jj < 5; jj++) {
            int col = (jt0 + jj) * 8 + 2 * tig;
            int r0 = m0 + gid, r1 = r0 + 8;
            int t00 = col - r0, t10 = col - r1;
            if ((unsigned)t00 < 64u)       Srel[r0 * QSTR + t00]     = sacc[jj][0];
            if ((unsigned)(t00 + 1) < 64u) Srel[r0 * QSTR + t00 + 1] = sacc[jj][1];
            if ((unsigned)t10 < 64u)       Srel[r1 * QSTR + t10]     = sacc[jj][2];
            if ((unsigned)(t10 + 1) < 64u) Srel[r1 * QSTR + t10 + 1] = sacc[jj][3];
        }
#pragma unroll
        for (int j = 0; j < 4; j++) {
            int col = np0 + 8 * j + 2 * tig;
            Spe[(m0 + gid) * QSTR + col]     = pacc[j][0];
            Spe[(m0 + gid) * QSTR + col + 1] = pacc[j][1];
            Spe[(m0 + gid + 8) * QSTR + col]     = pacc[j][2];
            Spe[(m0 + gid + 8) * QSTR + col + 1] = pacc[j][3];
        }
        __syncthreads();

        // ---- online softmax (scores already carry SCALE via Q)
        {
            float s[16];
            float mloc = -1e30f;
#pragma unroll
            for (int e = 0; e < 16; e++) {
                s[e] = Srel[srow * QSTR + tbase + e] + Spe[srow * QSTR + tbase + e];
                mloc = fmaxf(mloc, s[e]);
            }
            mloc = fmaxf(mloc, __shfl_xor_sync(0xFFFFFFFFu, mloc, 1));
            mloc = fmaxf(mloc, __shfl_xor_sync(0xFFFFFFFFu, mloc, 2));
            float m_new = fmaxf(m_run, mloc);
            float corr  = __expf(m_run - m_new);
            l_run *= corr;
            float p[16], psum = 0.f;
#pragma unroll
            for (int e = 0; e < 16; e++) { p[e] = __expf(s[e] - m_new); psum += p[e]; }
            psum += __shfl_xor_sync(0xFFFFFFFFu, psum, 1);
            psum += __shfl_xor_sync(0xFFFFFFFFu, psum, 2);
            l_run += psum;
            m_run = m_new;
            if (tg4 == 0) corr_s[srow] = corr;

            // masked P into skewed plane + zero complement
#pragma unroll
            for (int e = 0; e < 16; e++) {
                int t = tbase + e;
                float jj = (float)(jc + t);
                float mk = fminf(1.f, fmaxf(0.f, (jj - 1023.f + spanL) * (1.f / 32.f) + 1.f));
                float pm = to_tf32(p[e] * mk);
                int u = srow + t;
                Ps[srow * PSTR2 + u] = pm;
                int uz = (t < srow) ? t : t + 64;
                Ps[srow * PSTR2 + uz] = 0.f;
            }
        }
        __syncthreads();

        // ---- AV: oacc = oacc*corr + P_abs @ V^T (band k-blocks only)
        {
            float cA = corr_s[m0 + gid], cB = corr_s[m0 + gid + 8];
#pragma unroll
            for (int j = 0; j < 4; j++) {
                oacc[j][0] *= cA; oacc[j][1] *= cA;
                oacc[j][2] *= cB; oacc[j][3] *= cB;
            }
            // nonzero P cols for rows [m0, m0+15]: u in [m0, m0+78]
            // -> k-blocks 2mb .. 2mb+9 (10 of 16); skipped blocks are all-zero P
#pragma unroll
            for (int kk = 0; kk < 10; kk++) {
                int k0 = (2 * mb + kk) * 8;
                int ar = (m0 + gid) * PSTR2 + k0 + tig;
                uint32_t a0 = Pu[ar];
                uint32_t a1 = Pu[ar + 8 * PSTR2];
                uint32_t a2 = Pu[ar + 4];
                uint32_t a3 = Pu[ar + 8 * PSTR2 + 4];
#pragma unroll
                for (int j = 0; j < 4; j++) {
                    int br = (np0 + 8 * j + gid) * VSTR + k0 + tig;
                    MMA_TF32(oacc[j], a0, a1, a2, a3, Vu[br], Vu[br + 4]);
                }
            }
        }
    }

    __syncthreads();
    if (tg4 == 0) linv_s[srow] = 1.f / l_run;
    __syncthreads();

    // epilogue: g_ctx[b][i0+row][kh][d]
    {
        float lA = linv_s[m0 + gid], lB = linv_s[m0 + gid + 8];
        int b = bk >> 3;
        int r0 = i0 + m0 + gid;
#pragma unroll
        for (int j = 0; j < 4; j++) {
            int col = np0 + 8 * j + 2 * tig;
            float* p0 = g_ctx + ((size_t)(b * Mm + r0) * Kk + kh) * Dd + col;
            float* p1 = g_ctx + ((size_t)(b * Mm + r0 + 8) * Kk + kh) * Dd + col;
            *(float2*)p0 = make_float2(oacc[j][0] * lA, oacc[j][1] * lA);
            *(float2*)p1 = make_float2(oacc[j][2] * lB, oacc[j][3] * lB);
        }
    }
}

// ---------------------------------------------------------------------------
extern "C" void kernel_launch(void* const* d_in, const int* in_sizes, int n_in,
                              void* d_out, int out_size) {
    const float* query = (const float*)d_in[0];
    const float* key   = (const float*)d_in[1];
    const float* value = (const float*)d_in[2];
    const float* pe    = (const float*)d_in[3];
    const float* Wq    = (const float*)d_in[4];
    const float* Wk    = (const float*)d_in[5];
    const float* Wv    = (const float*)d_in[6];
    const float* Wo    = (const float*)d_in[7];
    const float* span  = (const float*)d_in[8];
    float* out = (float*)d_out;

    cudaFuncSetAttribute(attn_mma_kernel,
                         cudaFuncAttributeMaxDynamicSharedMemorySize,
                         ATTN_SMEM_FLOATS * (int)sizeof(float));

    proj_qkv_kernel<<<dim3(Bb * Mm / 128, 4), 256>>>(query, Wq, Mm, 0);
    proj_qkv_kernel<<<dim3(Bb * SKk / 128, 4), 256>>>(key, Wk, SKk, 1);
    proj_qkv_kernel<<<dim3(Bb * SKk / 128, 4), 256>>>(value, Wv, SKk, 2);
    pe_prep_kernel<<<(Ll * Dd + 255) / 256, 256>>>(pe);

    attn_mma_kernel<<<dim3(Mm / 64, BKC), 256,
                      ATTN_SMEM_FLOATS * (int)sizeof(float)>>>(span);

    proj_out_kernel<<<dim3(Bb * Mm / 128, 4), 256>>>(Wo, out);
}

// round 10
// speedup vs baseline: 1.7368x; 1.1233x over previous
#include <cuda_runtime.h>
#include <cuda_bf16.h>
#include <cstdint>

// Problem constants
#define Bb   8
#define Mm   512
#define Ll   1024
#define Hh   512
#define Kk   8
#define Dd   64
#define SKk  1536           // M + L
#define BKC  64             // B * K
#define SCALE 0.125f

// Scratch (device globals)
__device__ float gq[(size_t)BKC * Mm * Dd];      // [bk][s][d]
__device__ float gk[(size_t)BKC * SKk * Dd];     // [bk][s][d]
__device__ float gv[(size_t)BKC * Dd * SKk];     // [bk][d][s]  (transposed)
__device__ float gpe[Ll * Dd];                   // [j][d]
__device__ float g_ctx[(size_t)Bb * Mm * Hh];    // [B, M, K, D]

__device__ __forceinline__ float to_tf32(float x) {
    uint32_t r;
    asm("cvt.rna.tf32.f32 %0, %1;" : "=r"(r) : "f"(x));
    return __uint_as_float(r);
}
__device__ __forceinline__ uint32_t rna_u(float x) {
    uint32_t r;
    asm("cvt.rna.tf32.f32 %0, %1;" : "=r"(r) : "f"(x));
    return r;
}

#define MMA_TF32(c, a0, a1, a2, a3, b0, b1)                                   \
    asm volatile(                                                             \
        "mma.sync.aligned.m16n8k8.row.col.f32.tf32.tf32.f32 "                 \
        "{%0,%1,%2,%3},{%4,%5,%6,%7},{%8,%9},{%0,%1,%2,%3};"                  \
        : "+f"(c[0]), "+f"(c[1]), "+f"(c[2]), "+f"(c[3])                      \
        : "r"(a0), "r"(a1), "r"(a2), "r"(a3), "r"(b0), "r"(b1));

#define CP16(dst_sh, src)                                                     \
    asm volatile("cp.async.cg.shared.global [%0], [%1], 16;"                  \
                 :: "r"(dst_sh), "l"(src))
#define CP_COMMIT() asm volatile("cp.async.commit_group;")
#define CP_WAIT0()  asm volatile("cp.async.wait_group 0;" ::: "memory")

#define PJSTR 36

// ---------------------------------------------------------------------------
// Single-pass tf32 QKV projection GEMM: Y = X @ W^T, head-split stores.
// ---------------------------------------------------------------------------
__global__ __launch_bounds__(256) void proj_qkv_kernel(
        const float* __restrict__ X, const float* __restrict__ W,
        int S, int sel) {
    __shared__ float Xs[128 * PJSTR];
    __shared__ float Ws[128 * PJSTR];

    const int tid  = threadIdx.x;
    const int lane = tid & 31;
    const int wid  = tid >> 5;
    const int warp_m = wid >> 1;
    const int warp_n = wid & 1;
    const int gid = lane >> 2;
    const int tig = lane & 3;
    const int row0 = blockIdx.x * 128;
    const int col0 = blockIdx.y * 128;

    float c[2][8][4];
#pragma unroll
    for (int f = 0; f < 2; f++)
#pragma unroll
        for (int j = 0; j < 8; j++)
#pragma unroll
            for (int t = 0; t < 4; t++) c[f][j][t] = 0.f;

    for (int k0 = 0; k0 < 512; k0 += 32) {
#pragma unroll
        for (int i = 0; i < 4; i++) {
            int f4 = tid + i * 256;
            int r  = f4 >> 3;
            int kq = (f4 & 7) << 2;
            float4 xv = *(const float4*)(X + (size_t)(row0 + r) * 512 + k0 + kq);
            *(float4*)&Xs[r * PJSTR + kq] = xv;
            float4 wv = *(const float4*)(W + (size_t)(col0 + r) * 512 + k0 + kq);
            *(float4*)&Ws[r * PJSTR + kq] = wv;
        }
        __syncthreads();

#pragma unroll
        for (int kk = 0; kk < 32; kk += 8) {
            uint32_t a[2][4];
#pragma unroll
            for (int f = 0; f < 2; f++) {
                int rbase = warp_m * 32 + f * 16 + gid;
#pragma unroll
                for (int rg = 0; rg < 4; rg++) {
                    int r    = rbase + ((rg & 1) << 3);
                    int kcol = kk + tig + ((rg >> 1) << 2);
                    a[f][rg] = rna_u(Xs[r * PJSTR + kcol]);
                }
            }
#pragma unroll
            for (int j = 0; j < 8; j++) {
                int cidx = warp_n * 64 + j * 8 + gid;
                uint32_t b0 = rna_u(Ws[cidx * PJSTR + kk + tig]);
                uint32_t b1 = rna_u(Ws[cidx * PJSTR + kk + tig + 4]);
#pragma unroll
                for (int f = 0; f < 2; f++)
                    MMA_TF32(c[f][j], a[f][0], a[f][1], a[f][2], a[f][3], b0, b1);
            }
        }
        __syncthreads();
    }

#pragma unroll
    for (int f = 0; f < 2; f++) {
        int rloc = warp_m * 32 + f * 16 + gid;
#pragma unroll
        for (int j = 0; j < 8; j++) {
            int cc = col0 + warp_n * 64 + j * 8 + 2 * tig;
#pragma unroll
            for (int h = 0; h < 2; h++) {
                int r = row0 + rloc + h * 8;
                int b = r / S, s = r - b * S;
                int kh = cc >> 6, d = cc & 63;
                int bk = b * Kk + kh;
                float tx = to_tf32(c[f][j][h * 2]);
                float ty = to_tf32(c[f][j][h * 2 + 1]);
                if (sel == 0) {
                    *(float2*)&gq[((size_t)bk * Mm + s) * Dd + d] = make_float2(tx, ty);
                } else if (sel == 1) {
                    *(float2*)&gk[((size_t)bk * SKk + s) * Dd + d] = make_float2(tx, ty);
                } else {
                    gv[((size_t)bk * Dd + d) * SKk + s]     = tx;
                    gv[((size_t)bk * Dd + d + 1) * SKk + s] = ty;
                }
            }
        }
    }
}

// ---------------------------------------------------------------------------
// 3-pass split-tf32 output GEMM: out = g_ctx @ Wo^T  (precision anchor)
// ---------------------------------------------------------------------------
__global__ __launch_bounds__(256) void proj_out_kernel(
        const float* __restrict__ W, float* __restrict__ Yout) {
    __shared__ float Xs[128 * PJSTR];
    __shared__ float Ws[128 * PJSTR];

    const int tid  = threadIdx.x;
    const int lane = tid & 31;
    const int wid  = tid >> 5;
    const int warp_m = wid >> 1;
    const int warp_n = wid & 1;
    const int gid = lane >> 2;
    const int tig = lane & 3;
    const int row0 = blockIdx.x * 128;
    const int col0 = blockIdx.y * 128;

    float c[2][8][4];
#pragma unroll
    for (int f = 0; f < 2; f++)
#pragma unroll
        for (int j = 0; j < 8; j++)
#pragma unroll
            for (int t = 0; t < 4; t++) c[f][j][t] = 0.f;

    for (int k0 = 0; k0 < 512; k0 += 32) {
#pragma unroll
        for (int i = 0; i < 4; i++) {
            int f4 = tid + i * 256;
            int r  = f4 >> 3;
            int kq = (f4 & 7) << 2;
            float4 xv = *(const float4*)(g_ctx + (size_t)(row0 + r) * 512 + k0 + kq);
            *(float4*)&Xs[r * PJSTR + kq] = xv;
            float4 wv = *(const float4*)(W + (size_t)(col0 + r) * 512 + k0 + kq);
            *(float4*)&Ws[r * PJSTR + kq] = wv;
        }
        __syncthreads();

#pragma unroll
        for (int kk = 0; kk < 32; kk += 8) {
            uint32_t ahi[2][4], alo[2][4];
#pragma unroll
            for (int f = 0; f < 2; f++) {
                int rbase = warp_m * 32 + f * 16 + gid;
#pragma unroll
                for (int rg = 0; rg < 4; rg++) {
                    int r    = rbase + ((rg & 1) << 3);
                    int kcol = kk + tig + ((rg >> 1) << 2);
                    float x  = Xs[r * PJSTR + kcol];
                    uint32_t hb = __float_as_uint(x) & 0xFFFFE000u;
                    ahi[f][rg] = hb;
                    alo[f][rg] = __float_as_uint(x - __uint_as_float(hb));
                }
            }
#pragma unroll
            for (int j = 0; j < 8; j++) {
                int cidx = warp_n * 64 + j * 8 + gid;
                float b0f = Ws[cidx * PJSTR + kk + tig];
                float b1f = Ws[cidx * PJSTR + kk + tig + 4];
                uint32_t b0h = __float_as_uint(b0f) & 0xFFFFE000u;
                uint32_t b1h = __float_as_uint(b1f) & 0xFFFFE000u;
                uint32_t b0l = __float_as_uint(b0f - __uint_as_float(b0h));
                uint32_t b1l = __float_as_uint(b1f - __uint_as_float(b1h));
#pragma unroll
                for (int f = 0; f < 2; f++) {
                    MMA_TF32(c[f][j], ahi[f][0], ahi[f][1], ahi[f][2], ahi[f][3], b0h, b1h);
                    MMA_TF32(c[f][j], ahi[f][0], ahi[f][1], ahi[f][2], ahi[f][3], b0l, b1l);
                    MMA_TF32(c[f][j], alo[f][0], alo[f][1], alo[f][2], alo[f][3], b0h, b1h);
                }
            }
        }
        __syncthreads();
    }

#pragma unroll
    for (int f = 0; f < 2; f++) {
        int rloc = warp_m * 32 + f * 16 + gid;
#pragma unroll
        for (int j = 0; j < 8; j++) {
            int cc = col0 + warp_n * 64 + j * 8 + 2 * tig;
#pragma unroll
            for (int h = 0; h < 2; h++) {
                int r = row0 + rloc + h * 8;
                *(float2*)(Yout + (size_t)r * 512 + cc) =
                    make_float2(c[f][j][h * 2], c[f][j][h * 2 + 1]);
            }
        }
    }
}

// ---------------------------------------------------------------------------
// PE transpose prep: gpe[j][d] = tf32(pe[d][j])
// ---------------------------------------------------------------------------
__global__ void pe_prep_kernel(const float* __restrict__ pe) {
    int idx = blockIdx.x * 256 + threadIdx.x;
    if (idx < Ll * Dd) {
        int j = idx >> 6, d = idx & 63;
        gpe[idx] = to_tf32(pe[d * Ll + j]);
    }
}

// ---------------------------------------------------------------------------
// Single-pass tf32 MMA banded attention, cp.async pipelined.
//   V double-buffered; K/PE prefetched post-score; P dedicated (zeros
//   written once). Per-warp balanced band tiles (R9). 3 syncs/chunk.
// ---------------------------------------------------------------------------
#define QSTR 68
#define KSTR 68
#define VSTR 132
#define PSTR2 132
#define OFF_Q    0
#define OFF_K    (OFF_Q + 64 * QSTR)        // 4352
#define OFF_PE   (OFF_K + 128 * KSTR)       // 13056
#define OFF_V    (OFF_PE + 64 * QSTR)       // 17408  (2 buffers)
#define OFF_P    (OFF_V + 2 * 64 * VSTR)    // 34304
#define OFF_SREL (OFF_P + 64 * PSTR2)       // 42752
#define OFF_SPE  (OFF_SREL + 64 * QSTR)     // 47104
#define OFF_CORR (OFF_SPE + 64 * QSTR)      // 51456
#define OFF_LINV (OFF_CORR + 64)
#define ATTN_SMEM_FLOATS (OFF_LINV + 64)    // 51584 floats = 206,336 B

__global__ __launch_bounds__(256) void attn_mma_kernel(
        const float* __restrict__ span_val) {
    extern __shared__ float sm[];
    float* Qs    = sm + OFF_Q;
    float* Ks    = sm + OFF_K;
    float* PEs   = sm + OFF_PE;
    float* Vbase = sm + OFF_V;
    float* Ps    = sm + OFF_P;
    float* Srel  = sm + OFF_SREL;
    float* Spe   = sm + OFF_SPE;
    float* corr_s = sm + OFF_CORR;
    float* linv_s = sm + OFF_LINV;

    const uint32_t* Qu  = (const uint32_t*)Qs;
    const uint32_t* Ku  = (const uint32_t*)Ks;
    const uint32_t* PEu = (const uint32_t*)PEs;
    const uint32_t* Pu  = (const uint32_t*)Ps;

    const int tid  = threadIdx.x;
    const int lane = tid & 31;
    const int wid  = tid >> 5;
    const int gid  = lane >> 2;
    const int tig  = lane & 3;
    const int bk   = blockIdx.y;
    const int i0   = blockIdx.x * 64;
    const int kh   = bk & 7;

    const int mb  = wid & 3;
    const int m0  = mb * 16;
    const int np0 = (wid >> 2) * 32;
    const int jt0 = 2 * mb + 5 * (wid >> 2);     // first of 5 owned QK tiles

    const int srow = tid >> 2;
    const int tg4  = tid & 3;
    const int tbase = tg4 * 16;
    const float spanL = span_val[kh] * 1024.f;

    const float* gkp_base = gk + ((size_t)bk * SKk + i0) * Dd;
    const float* gvp_base = gv + (size_t)bk * Dd * SKk + i0;

    // per-thread staging coordinates
    const int kr  = tid >> 4, kc4 = (tid & 15) << 2;     // K/PE: 16 rows/iter
    const int vd  = tid >> 5, vc4 = (tid & 31) << 2;     // V: 8 d-rows/iter

    // shared addresses for cp.async destinations
    const uint32_t Ksh  = (uint32_t)__cvta_generic_to_shared(Ks);
    const uint32_t PEsh = (uint32_t)__cvta_generic_to_shared(PEs);
    const uint32_t Vsh  = (uint32_t)__cvta_generic_to_shared(Vbase);

    // ---- prologue: Q load, P zero plane, prefetch chunk 0
    {
        const float* gqp = gq + ((size_t)bk * Mm + i0) * Dd;
#pragma unroll
        for (int it = 0; it < 4; it++) {
            int idx = tid + it * 256;
            int r = idx >> 4, c4 = (idx & 15) << 2;
            float4 v = *(const float4*)(gqp + (size_t)r * Dd + c4);
            v.x *= SCALE; v.y *= SCALE; v.z *= SCALE; v.w *= SCALE;
            *(float4*)&Qs[r * QSTR + c4] = v;
        }
        // zero entire P plane once (zeros persist; values rewritten per chunk)
#pragma unroll
        for (int it = 0; it < 33; it++) {
            int idx = tid + it * 256;                  // 64*132 = 8448
            if (idx < 64 * PSTR2) Ps[idx] = 0.f;
        }
        // prefetch chunk 0: K, PE, V -> buf 0
#pragma unroll
        for (int it = 0; it < 8; it++) {
            int r = kr + it * 16;
            CP16(Ksh + (uint32_t)(r * KSTR + kc4) * 4,
                 gkp_base + (size_t)r * Dd + kc4);
        }
#pragma unroll
        for (int it = 0; it < 4; it++) {
            int r = kr + it * 16;
            CP16(PEsh + (uint32_t)(r * QSTR + kc4) * 4,
                 gpe + (size_t)r * Dd + kc4);
        }
#pragma unroll
        for (int it = 0; it < 8; it++) {
            int d = vd + it * 8;
            CP16(Vsh + (uint32_t)(d * VSTR + vc4) * 4,
                 gvp_base + (size_t)d * SKk + vc4);
        }
        CP_COMMIT();
    }

    float oacc[4][4];
#pragma unroll
    for (int j = 0; j < 4; j++)
#pragma unroll
        for (int t = 0; t < 4; t++) oacc[j][t] = 0.f;

    float m_run = -1e30f, l_run = 0.f;

    for (int cidx = 0; cidx < 16; cidx++) {
        const int jc = cidx * 64;
        const uint32_t* Vu = (const uint32_t*)(Vbase + (cidx & 1) * 64 * VSTR);

        CP_WAIT0();
        __syncthreads();                 // S1: staging for cidx visible; prev AV done

        // prefetch V(cidx+1) into the other buffer (its last reader was AV(cidx-1))
        if (cidx + 1 < 16) {
            uint32_t vdst = Vsh + (uint32_t)(((cidx + 1) & 1) * 64 * VSTR) * 4;
            const float* vsrc = gvp_base + (cidx + 1) * 64;
#pragma unroll
            for (int it = 0; it < 8; it++) {
                int d = vd + it * 8;
                CP16(vdst + (uint32_t)(d * VSTR + vc4) * 4,
                     vsrc + (size_t)d * SKk + vc4);
            }
            CP_COMMIT();
        }

        // ---- QK^T band tiles (5 per warp) + Q@PE (4 per warp), tf32
        float sacc[5][4], pacc[4][4];
#pragma unroll
        for (int j = 0; j < 5; j++)
#pragma unroll
            for (int t = 0; t < 4; t++) sacc[j][t] = 0.f;
#pragma unroll
        for (int j = 0; j < 4; j++)
#pragma unroll
            for (int t = 0; t < 4; t++) pacc[j][t] = 0.f;

#pragma unroll
        for (int k0 = 0; k0 < 64; k0 += 8) {
            int ar = (m0 + gid) * QSTR + k0 + tig;
            uint32_t a0 = Qu[ar];
            uint32_t a1 = Qu[ar + 8 * QSTR];
            uint32_t a2 = Qu[ar + 4];
            uint32_t a3 = Qu[ar + 8 * QSTR + 4];
#pragma unroll
            for (int jj = 0; jj < 5; jj++) {
                int br = ((jt0 + jj) * 8 + gid) * KSTR + k0 + tig;
                MMA_TF32(sacc[jj], a0, a1, a2, a3, Ku[br], Ku[br + 4]);
            }
#pragma unroll
            for (int j = 0; j < 4; j++) {
                int br = (np0 + 8 * j + gid) * QSTR + k0 + tig;
                MMA_TF32(pacc[j], a0, a1, a2, a3, PEu[br], PEu[br + 4]);
            }
        }

        // scatter QK band -> de-skewed Srel[i][col-row]
#pragma unroll
        for (int jj = 0; jj < 5; jj++) {
            int col = (jt0 + jj) * 8 + 2 * tig;
            int r0 = m0 + gid, r1 = r0 + 8;
            int t00 = col - r0, t10 = col - r1;
            if ((unsigned)t00 < 64u)       Srel[r0 * QSTR + t00]     = sacc[jj][0];
            if ((unsigned)(t00 + 1) < 64u) Srel[r0 * QSTR + t00 + 1] = sacc[jj][1];
            if ((unsigned)t10 < 64u)       Srel[r1 * QSTR + t10]     = sacc[jj][2];
            if ((unsigned)(t10 + 1) < 64u) Srel[r1 * QSTR + t10 + 1] = sacc[jj][3];
        }
#pragma unroll
        for (int j = 0; j < 4; j++) {
            int col = np0 + 8 * j + 2 * tig;
            Spe[(m0 + gid) * QSTR + col]     = pacc[j][0];
            Spe[(m0 + gid) * QSTR + col + 1] = pacc[j][1];
            Spe[(m0 + gid + 8) * QSTR + col]     = pacc[j][2];
            Spe[(m0 + gid + 8) * QSTR + col + 1] = pacc[j][3];
        }
        __syncthreads();                 // S2: scores in smem; Ks/PEs now free

        // prefetch K(cidx+1), PE(cidx+1) during softmax + AV
        if (cidx + 1 < 16) {
            const float* ksrc = gkp_base + (size_t)(cidx + 1) * 64 * Dd;
            const float* psrc = gpe + (size_t)(cidx + 1) * 64 * Dd;
#pragma unroll
            for (int it = 0; it < 8; it++) {
                int r = kr + it * 16;
                CP16(Ksh + (uint32_t)(r * KSTR + kc4) * 4,
                     ksrc + (size_t)r * Dd + kc4);
            }
#pragma unroll
            for (int it = 0; it < 4; it++) {
                int r = kr + it * 16;
                CP16(PEsh + (uint32_t)(r * QSTR + kc4) * 4,
                     psrc + (size_t)r * Dd + kc4);
            }
            CP_COMMIT();
        }

        // ---- online softmax (scores already carry SCALE via Q)
        {
            float s[16];
            float mloc = -1e30f;
#pragma unroll
            for (int e = 0; e < 16; e++) {
                s[e] = Srel[srow * QSTR + tbase + e] + Spe[srow * QSTR + tbase + e];
                mloc = fmaxf(mloc, s[e]);
            }
            mloc = fmaxf(mloc, __shfl_xor_sync(0xFFFFFFFFu, mloc, 1));
            mloc = fmaxf(mloc, __shfl_xor_sync(0xFFFFFFFFu, mloc, 2));
            float m_new = fmaxf(m_run, mloc);
            float corr  = __expf(m_run - m_new);
            l_run *= corr;
            float p[16], psum = 0.f;
#pragma unroll
            for (int e = 0; e < 16; e++) { p[e] = __expf(s[e] - m_new); psum += p[e]; }
            psum += __shfl_xor_sync(0xFFFFFFFFu, psum, 1);
            psum += __shfl_xor_sync(0xFFFFFFFFu, psum, 2);
            l_run += psum;
            m_run = m_new;
            if (tg4 == 0) corr_s[srow] = corr;

            // masked P values into skewed plane (zeros persist from prologue)
#pragma unroll
            for (int e = 0; e < 16; e++) {
                int t = tbase + e;
                float jj = (float)(jc + t);
                float mk = fminf(1.f, fmaxf(0.f, (jj - 1023.f + spanL) * (1.f / 32.f) + 1.f));
                Ps[srow * PSTR2 + srow + t] = to_tf32(p[e] * mk);
            }
        }
        __syncthreads();                 // S3: P ready

        // ---- AV: oacc = oacc*corr + P_abs @ V^T (band k-blocks only)
        {
            float cA = corr_s[m0 + gid], cB = corr_s[m0 + gid + 8];
#pragma unroll
            for (int j = 0; j < 4; j++) {
                oacc[j][0] *= cA; oacc[j][1] *= cA;
                oacc[j][2] *= cB; oacc[j][3] *= cB;
            }
#pragma unroll
            for (int kk = 0; kk < 10; kk++) {
                int k0 = (2 * mb + kk) * 8;
                int ar = (m0 + gid) * PSTR2 + k0 + tig;
                uint32_t a0 = Pu[ar];
                uint32_t a1 = Pu[ar + 8 * PSTR2];
                uint32_t a2 = Pu[ar + 4];
                uint32_t a3 = Pu[ar + 8 * PSTR2 + 4];
#pragma unroll
                for (int j = 0; j < 4; j++) {
                    int br = (np0 + 8 * j + gid) * VSTR + k0 + tig;
                    MMA_TF32(oacc[j], a0, a1, a2, a3, Vu[br], Vu[br + 4]);
                }
            }
        }
    }

    __syncthreads();
    if (tg4 == 0) linv_s[srow] = 1.f / l_run;
    __syncthreads();

    // epilogue: g_ctx[b][i0+row][kh][d]
    {
        float lA = linv_s[m0 + gid], lB = linv_s[m0 + gid + 8];
        int b = bk >> 3;
        int r0 = i0 + m0 + gid;
#pragma unroll
        for (int j = 0; j < 4; j++) {
            int col = np0 + 8 * j + 2 * tig;
            float* p0 = g_ctx + ((size_t)(b * Mm + r0) * Kk + kh) * Dd + col;
            float* p1 = g_ctx + ((size_t)(b * Mm + r0 + 8) * Kk + kh) * Dd + col;
            *(float2*)p0 = make_float2(oacc[j][0] * lA, oacc[j][1] * lA);
            *(float2*)p1 = make_float2(oacc[j][2] * lB, oacc[j][3] * lB);
        }
    }
}

// ---------------------------------------------------------------------------
extern "C" void kernel_launch(void* const* d_in, const int* in_sizes, int n_in,
                              void* d_out, int out_size) {
    const float* query = (const float*)d_in[0];
    const float* key   = (const float*)d_in[1];
    const float* value = (const float*)d_in[2];
    const float* pe    = (const float*)d_in[3];
    const float* Wq    = (const float*)d_in[4];
    const float* Wk    = (const float*)d_in[5];
    const float* Wv    = (const float*)d_in[6];
    const float* Wo    = (const float*)d_in[7];
    const float* span  = (const float*)d_in[8];
    float* out = (float*)d_out;

    cudaFuncSetAttribute(attn_mma_kernel,
                         cudaFuncAttributeMaxDynamicSharedMemorySize,
                         ATTN_SMEM_FLOATS * (int)sizeof(float));

    proj_qkv_kernel<<<dim3(Bb * Mm / 128, 4), 256>>>(query, Wq, Mm, 0);
    proj_qkv_kernel<<<dim3(Bb * SKk / 128, 4), 256>>>(key, Wk, SKk, 1);
    proj_qkv_kernel<<<dim3(Bb * SKk / 128, 4), 256>>>(value, Wv, SKk, 2);
    pe_prep_kernel<<<(Ll * Dd + 255) / 256, 256>>>(pe);

    attn_mma_kernel<<<dim3(Mm / 64, BKC), 256,
                      ATTN_SMEM_FLOATS * (int)sizeof(float)>>>(span);

    proj_out_kernel<<<dim3(Bb * Mm / 128, 4), 256>>>(Wo, out);
}

// round 11
// speedup vs baseline: 1.8110x; 1.0427x over previous
#include <cuda_runtime.h>
#include <cuda_bf16.h>
#include <cstdint>

// Problem constants
#define Bb   8
#define Mm   512
#define Ll   1024
#define Hh   512
#define Kk   8
#define Dd   64
#define SKk  1536           // M + L
#define BKC  64             // B * K
#define SCALE 0.125f

// Scratch (device globals)
__device__ float gq[(size_t)BKC * Mm * Dd];      // [bk][s][d]
__device__ float gk[(size_t)BKC * SKk * Dd];     // [bk][s][d]
__device__ float gv[(size_t)BKC * Dd * SKk];     // [bk][d][s]  (transposed)
__device__ float gpe[Ll * Dd];                   // [j][d]
__device__ float g_ctx[(size_t)Bb * Mm * Hh];    // [B, M, K, D]

__device__ __forceinline__ float to_tf32(float x) {
    uint32_t r;
    asm("cvt.rna.tf32.f32 %0, %1;" : "=r"(r) : "f"(x));
    return __uint_as_float(r);
}
__device__ __forceinline__ uint32_t rna_u(float x) {
    uint32_t r;
    asm("cvt.rna.tf32.f32 %0, %1;" : "=r"(r) : "f"(x));
    return r;
}

#define MMA_TF32(c, a0, a1, a2, a3, b0, b1)                                   \
    asm volatile(                                                             \
        "mma.sync.aligned.m16n8k8.row.col.f32.tf32.tf32.f32 "                 \
        "{%0,%1,%2,%3},{%4,%5,%6,%7},{%8,%9},{%0,%1,%2,%3};"                  \
        : "+f"(c[0]), "+f"(c[1]), "+f"(c[2]), "+f"(c[3])                      \
        : "r"(a0), "r"(a1), "r"(a2), "r"(a3), "r"(b0), "r"(b1));

#define CP16(dst_sh, src)                                                     \
    asm volatile("cp.async.cg.shared.global [%0], [%1], 16;"                  \
                 :: "r"(dst_sh), "l"(src))
#define CP_COMMIT() asm volatile("cp.async.commit_group;")
#define CP_WAIT0()  asm volatile("cp.async.wait_group 0;" ::: "memory")

#define PJSTR 36
#define PJ_BUF (128 * PJSTR)
#define PROJ_SMEM_FLOATS (4 * PJ_BUF)      // 2 X bufs + 2 W bufs = 73,728 B

// ---------------------------------------------------------------------------
// Single-pass tf32 QKV projection GEMM: Y = X @ W^T, head-split stores.
// cp.async double-buffered mainloop (1 sync per k-step).
// ---------------------------------------------------------------------------
__global__ __launch_bounds__(256) void proj_qkv_kernel(
        const float* __restrict__ X, const float* __restrict__ W,
        int S, int sel) {
    extern __shared__ float psm[];
    const uint32_t base_sh = (uint32_t)__cvta_generic_to_shared(psm);

    const int tid  = threadIdx.x;
    const int lane = tid & 31;
    const int wid  = tid >> 5;
    const int warp_m = wid >> 1;
    const int warp_n = wid & 1;
    const int gid = lane >> 2;
    const int tig = lane & 3;
    const int row0 = blockIdx.x * 128;
    const int col0 = blockIdx.y * 128;

    float c[2][8][4];
#pragma unroll
    for (int f = 0; f < 2; f++)
#pragma unroll
        for (int j = 0; j < 8; j++)
#pragma unroll
            for (int t = 0; t < 4; t++) c[f][j][t] = 0.f;

    // prologue: prefetch k-step 0 into buffer 0
#pragma unroll
    for (int i = 0; i < 4; i++) {
        int f4 = tid + i * 256;
        int r  = f4 >> 3;
        int kq = (f4 & 7) << 2;
        CP16(base_sh + (uint32_t)(r * PJSTR + kq) * 4,
             X + (size_t)(row0 + r) * 512 + kq);
        CP16(base_sh + (uint32_t)(2 * PJ_BUF + r * PJSTR + kq) * 4,
             W + (size_t)(col0 + r) * 512 + kq);
    }
    CP_COMMIT();

    for (int kt = 0; kt < 16; kt++) {
        CP_WAIT0();
        __syncthreads();

        if (kt + 1 < 16) {
            int nb = (kt + 1) & 1;
            int k0 = (kt + 1) * 32;
#pragma unroll
            for (int i = 0; i < 4; i++) {
                int f4 = tid + i * 256;
                int r  = f4 >> 3;
                int kq = (f4 & 7) << 2;
                CP16(base_sh + (uint32_t)(nb * PJ_BUF + r * PJSTR + kq) * 4,
                     X + (size_t)(row0 + r) * 512 + k0 + kq);
                CP16(base_sh + (uint32_t)((2 + nb) * PJ_BUF + r * PJSTR + kq) * 4,
                     W + (size_t)(col0 + r) * 512 + k0 + kq);
            }
            CP_COMMIT();
        }

        const float* Xs = psm + (kt & 1) * PJ_BUF;
        const float* Ws = psm + (2 + (kt & 1)) * PJ_BUF;

#pragma unroll
        for (int kk = 0; kk < 32; kk += 8) {
            uint32_t a[2][4];
#pragma unroll
            for (int f = 0; f < 2; f++) {
                int rbase = warp_m * 32 + f * 16 + gid;
#pragma unroll
                for (int rg = 0; rg < 4; rg++) {
                    int r    = rbase + ((rg & 1) << 3);
                    int kcol = kk + tig + ((rg >> 1) << 2);
                    a[f][rg] = rna_u(Xs[r * PJSTR + kcol]);
                }
            }
#pragma unroll
            for (int j = 0; j < 8; j++) {
                int cidx = warp_n * 64 + j * 8 + gid;
                uint32_t b0 = rna_u(Ws[cidx * PJSTR + kk + tig]);
                uint32_t b1 = rna_u(Ws[cidx * PJSTR + kk + tig + 4]);
#pragma unroll
                for (int f = 0; f < 2; f++)
                    MMA_TF32(c[f][j], a[f][0], a[f][1], a[f][2], a[f][3], b0, b1);
            }
        }
    }

#pragma unroll
    for (int f = 0; f < 2; f++) {
        int rloc = warp_m * 32 + f * 16 + gid;
#pragma unroll
        for (int j = 0; j < 8; j++) {
            int cc = col0 + warp_n * 64 + j * 8 + 2 * tig;
#pragma unroll
            for (int h = 0; h < 2; h++) {
                int r = row0 + rloc + h * 8;
                int b = r / S, s = r - b * S;
                int kh = cc >> 6, d = cc & 63;
                int bk = b * Kk + kh;
                float tx = to_tf32(c[f][j][h * 2]);
                float ty = to_tf32(c[f][j][h * 2 + 1]);
                if (sel == 0) {
                    *(float2*)&gq[((size_t)bk * Mm + s) * Dd + d] = make_float2(tx, ty);
                } else if (sel == 1) {
                    *(float2*)&gk[((size_t)bk * SKk + s) * Dd + d] = make_float2(tx, ty);
                } else {
                    gv[((size_t)bk * Dd + d) * SKk + s]     = tx;
                    gv[((size_t)bk * Dd + d + 1) * SKk + s] = ty;
                }
            }
        }
    }
}

// ---------------------------------------------------------------------------
// 3-pass split-tf32 output GEMM: out = g_ctx @ Wo^T  (precision anchor),
// cp.async double-buffered mainloop.
// ---------------------------------------------------------------------------
__global__ __launch_bounds__(256) void proj_out_kernel(
        const float* __restrict__ W, float* __restrict__ Yout) {
    extern __shared__ float psm[];
    const uint32_t base_sh = (uint32_t)__cvta_generic_to_shared(psm);

    const int tid  = threadIdx.x;
    const int lane = tid & 31;
    const int wid  = tid >> 5;
    const int warp_m = wid >> 1;
    const int warp_n = wid & 1;
    const int gid = lane >> 2;
    const int tig = lane & 3;
    const int row0 = blockIdx.x * 128;
    const int col0 = blockIdx.y * 128;

    float c[2][8][4];
#pragma unroll
    for (int f = 0; f < 2; f++)
#pragma unroll
        for (int j = 0; j < 8; j++)
#pragma unroll
            for (int t = 0; t < 4; t++) c[f][j][t] = 0.f;

    // prologue: prefetch k-step 0
#pragma unroll
    for (int i = 0; i < 4; i++) {
        int f4 = tid + i * 256;
        int r  = f4 >> 3;
        int kq = (f4 & 7) << 2;
        CP16(base_sh + (uint32_t)(r * PJSTR + kq) * 4,
             g_ctx + (size_t)(row0 + r) * 512 + kq);
        CP16(base_sh + (uint32_t)(2 * PJ_BUF + r * PJSTR + kq) * 4,
             W + (size_t)(col0 + r) * 512 + kq);
    }
    CP_COMMIT();

    for (int kt = 0; kt < 16; kt++) {
        CP_WAIT0();
        __syncthreads();

        if (kt + 1 < 16) {
            int nb = (kt + 1) & 1;
            int k0 = (kt + 1) * 32;
#pragma unroll
            for (int i = 0; i < 4; i++) {
                int f4 = tid + i * 256;
                int r  = f4 >> 3;
                int kq = (f4 & 7) << 2;
                CP16(base_sh + (uint32_t)(nb * PJ_BUF + r * PJSTR + kq) * 4,
                     g_ctx + (size_t)(row0 + r) * 512 + k0 + kq);
                CP16(base_sh + (uint32_t)((2 + nb) * PJ_BUF + r * PJSTR + kq) * 4,
                     W + (size_t)(col0 + r) * 512 + k0 + kq);
            }
            CP_COMMIT();
        }

        const float* Xs = psm + (kt & 1) * PJ_BUF;
        const float* Ws = psm + (2 + (kt & 1)) * PJ_BUF;

#pragma unroll
        for (int kk = 0; kk < 32; kk += 8) {
            uint32_t ahi[2][4], alo[2][4];
#pragma unroll
            for (int f = 0; f < 2; f++) {
                int rbase = warp_m * 32 + f * 16 + gid;
#pragma unroll
                for (int rg = 0; rg < 4; rg++) {
                    int r    = rbase + ((rg & 1) << 3);
                    int kcol = kk + tig + ((rg >> 1) << 2);
                    float x  = Xs[r * PJSTR + kcol];
                    uint32_t hb = __float_as_uint(x) & 0xFFFFE000u;
                    ahi[f][rg] = hb;
                    alo[f][rg] = __float_as_uint(x - __uint_as_float(hb));
                }
            }
#pragma unroll
            for (int j = 0; j < 8; j++) {
                int cidx = warp_n * 64 + j * 8 + gid;
                float b0f = Ws[cidx * PJSTR + kk + tig];
                float b1f = Ws[cidx * PJSTR + kk + tig + 4];
                uint32_t b0h = __float_as_uint(b0f) & 0xFFFFE000u;
                uint32_t b1h = __float_as_uint(b1f) & 0xFFFFE000u;
                uint32_t b0l = __float_as_uint(b0f - __uint_as_float(b0h));
                uint32_t b1l = __float_as_uint(b1f - __uint_as_float(b1h));
#pragma unroll
                for (int f = 0; f < 2; f++) {
                    MMA_TF32(c[f][j], ahi[f][0], ahi[f][1], ahi[f][2], ahi[f][3], b0h, b1h);
                    MMA_TF32(c[f][j], ahi[f][0], ahi[f][1], ahi[f][2], ahi[f][3], b0l, b1l);
                    MMA_TF32(c[f][j], alo[f][0], alo[f][1], alo[f][2], alo[f][3], b0h, b1h);
                }
            }
        }
    }

#pragma unroll
    for (int f = 0; f < 2; f++) {
        int rloc = warp_m * 32 + f * 16 + gid;
#pragma unroll
        for (int j = 0; j < 8; j++) {
            int cc = col0 + warp_n * 64 + j * 8 + 2 * tig;
#pragma unroll
            for (int h = 0; h < 2; h++) {
                int r = row0 + rloc + h * 8;
                *(float2*)(Yout + (size_t)r * 512 + cc) =
                    make_float2(c[f][j][h * 2], c[f][j][h * 2 + 1]);
            }
        }
    }
}

// ---------------------------------------------------------------------------
// PE transpose prep: gpe[j][d] = tf32(pe[d][j])
// ---------------------------------------------------------------------------
__global__ void pe_prep_kernel(const float* __restrict__ pe) {
    int idx = blockIdx.x * 256 + threadIdx.x;
    if (idx < Ll * Dd) {
        int j = idx >> 6, d = idx & 63;
        gpe[idx] = to_tf32(pe[d * Ll + j]);
    }
}

// ---------------------------------------------------------------------------
// Single-pass tf32 MMA banded attention, cp.async pipelined (unchanged R10).
// ---------------------------------------------------------------------------
#define QSTR 68
#define KSTR 68
#define VSTR 132
#define PSTR2 132
#define OFF_Q    0
#define OFF_K    (OFF_Q + 64 * QSTR)        // 4352
#define OFF_PE   (OFF_K + 128 * KSTR)       // 13056
#define OFF_V    (OFF_PE + 64 * QSTR)       // 17408  (2 buffers)
#define OFF_P    (OFF_V + 2 * 64 * VSTR)    // 34304
#define OFF_SREL (OFF_P + 64 * PSTR2)       // 42752
#define OFF_SPE  (OFF_SREL + 64 * QSTR)     // 47104
#define OFF_CORR (OFF_SPE + 64 * QSTR)      // 51456
#define OFF_LINV (OFF_CORR + 64)
#define ATTN_SMEM_FLOATS (OFF_LINV + 64)    // 51584 floats = 206,336 B

__global__ __launch_bounds__(256) void attn_mma_kernel(
        const float* __restrict__ span_val) {
    extern __shared__ float sm[];
    float* Qs    = sm + OFF_Q;
    float* Ks    = sm + OFF_K;
    float* PEs   = sm + OFF_PE;
    float* Vbase = sm + OFF_V;
    float* Ps    = sm + OFF_P;
    float* Srel  = sm + OFF_SREL;
    float* Spe   = sm + OFF_SPE;
    float* corr_s = sm + OFF_CORR;
    float* linv_s = sm + OFF_LINV;

    const uint32_t* Qu  = (const uint32_t*)Qs;
    const uint32_t* Ku  = (const uint32_t*)Ks;
    const uint32_t* PEu = (const uint32_t*)PEs;
    const uint32_t* Pu  = (const uint32_t*)Ps;

    const int tid  = threadIdx.x;
    const int lane = tid & 31;
    const int wid  = tid >> 5;
    const int gid  = lane >> 2;
    const int tig  = lane & 3;
    const int bk   = blockIdx.y;
    const int i0   = blockIdx.x * 64;
    const int kh   = bk & 7;

    const int mb  = wid & 3;
    const int m0  = mb * 16;
    const int np0 = (wid >> 2) * 32;
    const int jt0 = 2 * mb + 5 * (wid >> 2);     // first of 5 owned QK tiles

    const int srow = tid >> 2;
    const int tg4  = tid & 3;
    const int tbase = tg4 * 16;
    const float spanL = span_val[kh] * 1024.f;

    const float* gkp_base = gk + ((size_t)bk * SKk + i0) * Dd;
    const float* gvp_base = gv + (size_t)bk * Dd * SKk + i0;

    const int kr  = tid >> 4, kc4 = (tid & 15) << 2;
    const int vd  = tid >> 5, vc4 = (tid & 31) << 2;

    const uint32_t Ksh  = (uint32_t)__cvta_generic_to_shared(Ks);
    const uint32_t PEsh = (uint32_t)__cvta_generic_to_shared(PEs);
    const uint32_t Vsh  = (uint32_t)__cvta_generic_to_shared(Vbase);

    // ---- prologue: Q load, P zero plane, prefetch chunk 0
    {
        const float* gqp = gq + ((size_t)bk * Mm + i0) * Dd;
#pragma unroll
        for (int it = 0; it < 4; it++) {
            int idx = tid + it * 256;
            int r = idx >> 4, c4 = (idx & 15) << 2;
            float4 v = *(const float4*)(gqp + (size_t)r * Dd + c4);
            v.x *= SCALE; v.y *= SCALE; v.z *= SCALE; v.w *= SCALE;
            *(float4*)&Qs[r * QSTR + c4] = v;
        }
#pragma unroll
        for (int it = 0; it < 33; it++) {
            int idx = tid + it * 256;
            if (idx < 64 * PSTR2) Ps[idx] = 0.f;
        }
#pragma unroll
        for (int it = 0; it < 8; it++) {
            int r = kr + it * 16;
            CP16(Ksh + (uint32_t)(r * KSTR + kc4) * 4,
                 gkp_base + (size_t)r * Dd + kc4);
        }
#pragma unroll
        for (int it = 0; it < 4; it++) {
            int r = kr + it * 16;
            CP16(PEsh + (uint32_t)(r * QSTR + kc4) * 4,
                 gpe + (size_t)r * Dd + kc4);
        }
#pragma unroll
        for (int it = 0; it < 8; it++) {
            int d = vd + it * 8;
            CP16(Vsh + (uint32_t)(d * VSTR + vc4) * 4,
                 gvp_base + (size_t)d * SKk + vc4);
        }
        CP_COMMIT();
    }

    float oacc[4][4];
#pragma unroll
    for (int j = 0; j < 4; j++)
#pragma unroll
        for (int t = 0; t < 4; t++) oacc[j][t] = 0.f;

    float m_run = -1e30f, l_run = 0.f;

    for (int cidx = 0; cidx < 16; cidx++) {
        const int jc = cidx * 64;
        const uint32_t* Vu = (const uint32_t*)(Vbase + (cidx & 1) * 64 * VSTR);

        CP_WAIT0();
        __syncthreads();                 // S1

        if (cidx + 1 < 16) {
            uint32_t vdst = Vsh + (uint32_t)(((cidx + 1) & 1) * 64 * VSTR) * 4;
            const float* vsrc = gvp_base + (cidx + 1) * 64;
#pragma unroll
            for (int it = 0; it < 8; it++) {
                int d = vd + it * 8;
                CP16(vdst + (uint32_t)(d * VSTR + vc4) * 4,
                     vsrc + (size_t)d * SKk + vc4);
            }
            CP_COMMIT();
        }

        float sacc[5][4], pacc[4][4];
#pragma unroll
        for (int j = 0; j < 5; j++)
#pragma unroll
            for (int t = 0; t < 4; t++) sacc[j][t] = 0.f;
#pragma unroll
        for (int j = 0; j < 4; j++)
#pragma unroll
            for (int t = 0; t < 4; t++) pacc[j][t] = 0.f;

#pragma unroll
        for (int k0 = 0; k0 < 64; k0 += 8) {
            int ar = (m0 + gid) * QSTR + k0 + tig;
            uint32_t a0 = Qu[ar];
            uint32_t a1 = Qu[ar + 8 * QSTR];
            uint32_t a2 = Qu[ar + 4];
            uint32_t a3 = Qu[ar + 8 * QSTR + 4];
#pragma unroll
            for (int jj = 0; jj < 5; jj++) {
                int br = ((jt0 + jj) * 8 + gid) * KSTR + k0 + tig;
                MMA_TF32(sacc[jj], a0, a1, a2, a3, Ku[br], Ku[br + 4]);
            }
#pragma unroll
            for (int j = 0; j < 4; j++) {
                int br = (np0 + 8 * j + gid) * QSTR + k0 + tig;
                MMA_TF32(pacc[j], a0, a1, a2, a3, PEu[br], PEu[br + 4]);
            }
        }

#pragma unroll
        for (int jj = 0; jj < 5; jj++) {
            int col = (jt0 + jj) * 8 + 2 * tig;
            int r0 = m0 + gid, r1 = r0 + 8;
            int t00 = col - r0, t10 = col - r1;
            if ((unsigned)t00 < 64u)       Srel[r0 * QSTR + t00]     = sacc[jj][0];
            if ((unsigned)(t00 + 1) < 64u) Srel[r0 * QSTR + t00 + 1] = sacc[jj][1];
            if ((unsigned)t10 < 64u)       Srel[r1 * QSTR + t10]     = sacc[jj][2];
            if ((unsigned)(t10 + 1) < 64u) Srel[r1 * QSTR + t10 + 1] = sacc[jj][3];
        }
#pragma unroll
        for (int j = 0; j < 4; j++) {
            int col = np0 + 8 * j + 2 * tig;
            Spe[(m0 + gid) * QSTR + col]     = pacc[j][0];
            Spe[(m0 + gid) * QSTR + col + 1] = pacc[j][1];
            Spe[(m0 + gid + 8) * QSTR + col]     = pacc[j][2];
            Spe[(m0 + gid + 8) * QSTR + col + 1] = pacc[j][3];
        }
        __syncthreads();                 // S2

        if (cidx + 1 < 16) {
            const float* ksrc = gkp_base + (size_t)(cidx + 1) * 64 * Dd;
            const float* psrc = gpe + (size_t)(cidx + 1) * 64 * Dd;
#pragma unroll
            for (int it = 0; it < 8; it++) {
                int r = kr + it * 16;
                CP16(Ksh + (uint32_t)(r * KSTR + kc4) * 4,
                     ksrc + (size_t)r * Dd + kc4);
            }
#pragma unroll
            for (int it = 0; it < 4; it++) {
                int r = kr + it * 16;
                CP16(PEsh + (uint32_t)(r * QSTR + kc4) * 4,
                     psrc + (size_t)r * Dd + kc4);
            }
            CP_COMMIT();
        }

        {
            float s[16];
            float mloc = -1e30f;
#pragma unroll
            for (int e = 0; e < 16; e++) {
                s[e] = Srel[srow * QSTR + tbase + e] + Spe[srow * QSTR + tbase + e];
                mloc = fmaxf(mloc, s[e]);
            }
            mloc = fmaxf(mloc, __shfl_xor_sync(0xFFFFFFFFu, mloc, 1));
            mloc = fmaxf(mloc, __shfl_xor_sync(0xFFFFFFFFu, mloc, 2));
            float m_new = fmaxf(m_run, mloc);
            float corr  = __expf(m_run - m_new);
            l_run *= corr;
            float p[16], psum = 0.f;
#pragma unroll
            for (int e = 0; e < 16; e++) { p[e] = __expf(s[e] - m_new); psum += p[e]; }
            psum += __shfl_xor_sync(0xFFFFFFFFu, psum, 1);
            psum += __shfl_xor_sync(0xFFFFFFFFu, psum, 2);
            l_run += psum;
            m_run = m_new;
            if (tg4 == 0) corr_s[srow] = corr;

#pragma unroll
            for (int e = 0; e < 16; e++) {
                int t = tbase + e;
                float jj = (float)(jc + t);
                float mk = fminf(1.f, fmaxf(0.f, (jj - 1023.f + spanL) * (1.f / 32.f) + 1.f));
                Ps[srow * PSTR2 + srow + t] = to_tf32(p[e] * mk);
            }
        }
        __syncthreads();                 // S3

        {
            float cA = corr_s[m0 + gid], cB = corr_s[m0 + gid + 8];
#pragma unroll
            for (int j = 0; j < 4; j++) {
                oacc[j][0] *= cA; oacc[j][1] *= cA;
                oacc[j][2] *= cB; oacc[j][3] *= cB;
            }
#pragma unroll
            for (int kk = 0; kk < 10; kk++) {
                int k0 = (2 * mb + kk) * 8;
                int ar = (m0 + gid) * PSTR2 + k0 + tig;
                uint32_t a0 = Pu[ar];
                uint32_t a1 = Pu[ar + 8 * PSTR2];
                uint32_t a2 = Pu[ar + 4];
                uint32_t a3 = Pu[ar + 8 * PSTR2 + 4];
#pragma unroll
                for (int j = 0; j < 4; j++) {
                    int br = (np0 + 8 * j + gid) * VSTR + k0 + tig;
                    MMA_TF32(oacc[j], a0, a1, a2, a3, Vu[br], Vu[br + 4]);
                }
            }
        }
    }

    __syncthreads();
    if (tg4 == 0) linv_s[srow] = 1.f / l_run;
    __syncthreads();

    {
        float lA = linv_s[m0 + gid], lB = linv_s[m0 + gid + 8];
        int b = bk >> 3;
        int r0 = i0 + m0 + gid;
#pragma unroll
        for (int j = 0; j < 4; j++) {
            int col = np0 + 8 * j + 2 * tig;
            float* p0 = g_ctx + ((size_t)(b * Mm + r0) * Kk + kh) * Dd + col;
            float* p1 = g_ctx + ((size_t)(b * Mm + r0 + 8) * Kk + kh) * Dd + col;
            *(float2*)p0 = make_float2(oacc[j][0] * lA, oacc[j][1] * lA);
            *(float2*)p1 = make_float2(oacc[j][2] * lB, oacc[j][3] * lB);
        }
    }
}

// ---------------------------------------------------------------------------
extern "C" void kernel_launch(void* const* d_in, const int* in_sizes, int n_in,
                              void* d_out, int out_size) {
    const float* query = (const float*)d_in[0];
    const float* key   = (const float*)d_in[1];
    const float* value = (const float*)d_in[2];
    const float* pe    = (const float*)d_in[3];
    const float* Wq    = (const float*)d_in[4];
    const float* Wk    = (const float*)d_in[5];
    const float* Wv    = (const float*)d_in[6];
    const float* Wo    = (const float*)d_in[7];
    const float* span  = (const float*)d_in[8];
    float* out = (float*)d_out;

    cudaFuncSetAttribute(attn_mma_kernel,
                         cudaFuncAttributeMaxDynamicSharedMemorySize,
                         ATTN_SMEM_FLOATS * (int)sizeof(float));
    cudaFuncSetAttribute(proj_qkv_kernel,
                         cudaFuncAttributeMaxDynamicSharedMemorySize,
                         PROJ_SMEM_FLOATS * (int)sizeof(float));
    cudaFuncSetAttribute(proj_out_kernel,
                         cudaFuncAttributeMaxDynamicSharedMemorySize,
                         PROJ_SMEM_FLOATS * (int)sizeof(float));

    proj_qkv_kernel<<<dim3(Bb * Mm / 128, 4), 256,
                      PROJ_SMEM_FLOATS * (int)sizeof(float)>>>(query, Wq, Mm, 0);
    proj_qkv_kernel<<<dim3(Bb * SKk / 128, 4), 256,
                      PROJ_SMEM_FLOATS * (int)sizeof(float)>>>(key, Wk, SKk, 1);
    proj_qkv_kernel<<<dim3(Bb * SKk / 128, 4), 256,
                      PROJ_SMEM_FLOATS * (int)sizeof(float)>>>(value, Wv, SKk, 2);
    pe_prep_kernel<<<(Ll * Dd + 255) / 256, 256>>>(pe);

    attn_mma_kernel<<<dim3(Mm / 64, BKC), 256,
                      ATTN_SMEM_FLOATS * (int)sizeof(float)>>>(span);

    proj_out_kernel<<<dim3(Bb * Mm / 128, 4), 256,
                      PROJ_SMEM_FLOATS * (int)sizeof(float)>>>(Wo, out);
}

// round 12
// speedup vs baseline: 1.9566x; 1.0804x over previous
#include <cuda_runtime.h>
#include <cuda_bf16.h>
#include <cstdint>

// Problem constants
#define Bb   8
#define Mm   512
#define Ll   1024
#define Hh   512
#define Kk   8
#define Dd   64
#define SKk  1536           // M + L
#define BKC  64             // B * K
#define SCALE 0.125f

// Scratch (device globals)
__device__ float gq[(size_t)BKC * Mm * Dd];      // [bk][s][d]
__device__ float gk[(size_t)BKC * SKk * Dd];     // [bk][s][d]
__device__ float gv[(size_t)BKC * Dd * SKk];     // [bk][d][s]  (transposed)
__device__ float gpe[Ll * Dd];                   // [j][d]
__device__ float g_ctx[(size_t)Bb * Mm * Hh];    // [B, M, K, D]

__device__ __forceinline__ float to_tf32(float x) {
    uint32_t r;
    asm("cvt.rna.tf32.f32 %0, %1;" : "=r"(r) : "f"(x));
    return __uint_as_float(r);
}
__device__ __forceinline__ uint32_t rna_u(float x) {
    uint32_t r;
    asm("cvt.rna.tf32.f32 %0, %1;" : "=r"(r) : "f"(x));
    return r;
}

#define MMA_TF32(c, a0, a1, a2, a3, b0, b1)                                   \
    asm volatile(                                                             \
        "mma.sync.aligned.m16n8k8.row.col.f32.tf32.tf32.f32 "                 \
        "{%0,%1,%2,%3},{%4,%5,%6,%7},{%8,%9},{%0,%1,%2,%3};"                  \
        : "+f"(c[0]), "+f"(c[1]), "+f"(c[2]), "+f"(c[3])                      \
        : "r"(a0), "r"(a1), "r"(a2), "r"(a3), "r"(b0), "r"(b1));

#define CP16(dst_sh, src)                                                     \
    asm volatile("cp.async.cg.shared.global [%0], [%1], 16;"                  \
                 :: "r"(dst_sh), "l"(src))
#define CP_COMMIT() asm volatile("cp.async.commit_group;")
#define CP_WAIT0()  asm volatile("cp.async.wait_group 0;" ::: "memory")

#define PJSTR 36
#define PJ_BUF (128 * PJSTR)
#define PROJ_SMEM_FLOATS (4 * PJ_BUF)      // 73,728 B (also fits 128x132 transpose)

// ---------------------------------------------------------------------------
// FUSED single-pass tf32 QKV projection + PE prep.
// blocks 0..127: Q; 128..511: K; 512..895: V (transposed store via smem);
// blocks 896..911: PE transpose prep.
// cp.async double-buffered mainloop (1 sync per k-step).
// ---------------------------------------------------------------------------
__global__ __launch_bounds__(256) void proj_fused_kernel(
        const float* __restrict__ query, const float* __restrict__ key,
        const float* __restrict__ value, const float* __restrict__ pe,
        const float* __restrict__ Wq, const float* __restrict__ Wk,
        const float* __restrict__ Wv) {
    extern __shared__ float psm[];
    const int bid = blockIdx.x;

    if (bid >= 896) {
        // PE prep: gpe[j][d] = tf32(pe[d][j]); 16 blocks x 256 thr x 16 elems
        int base = (bid - 896) * 4096 + threadIdx.x;
#pragma unroll
        for (int i = 0; i < 16; i++) {
            int idx = base + i * 256;
            int j = idx >> 6, d = idx & 63;
            gpe[idx] = to_tf32(pe[(size_t)d * Ll + j]);
        }
        return;
    }

    int sel, idx, S;
    const float *X, *W;
    if (bid < 128)      { sel = 0; idx = bid;       X = query; W = Wq; S = Mm;  }
    else if (bid < 512) { sel = 1; idx = bid - 128; X = key;   W = Wk; S = SKk; }
    else                { sel = 2; idx = bid - 512; X = value; W = Wv; S = SKk; }

    const uint32_t base_sh = (uint32_t)__cvta_generic_to_shared(psm);
    const int tid  = threadIdx.x;
    const int lane = tid & 31;
    const int wid  = tid >> 5;
    const int warp_m = wid >> 1;
    const int warp_n = wid & 1;
    const int gid = lane >> 2;
    const int tig = lane & 3;
    const int row0 = (idx >> 2) * 128;
    const int col0 = (idx & 3) * 128;

    float c[2][8][4];
#pragma unroll
    for (int f = 0; f < 2; f++)
#pragma unroll
        for (int j = 0; j < 8; j++)
#pragma unroll
            for (int t = 0; t < 4; t++) c[f][j][t] = 0.f;

    // prologue: prefetch k-step 0 into buffer 0
#pragma unroll
    for (int i = 0; i < 4; i++) {
        int f4 = tid + i * 256;
        int r  = f4 >> 3;
        int kq = (f4 & 7) << 2;
        CP16(base_sh + (uint32_t)(r * PJSTR + kq) * 4,
             X + (size_t)(row0 + r) * 512 + kq);
        CP16(base_sh + (uint32_t)(2 * PJ_BUF + r * PJSTR + kq) * 4,
             W + (size_t)(col0 + r) * 512 + kq);
    }
    CP_COMMIT();

    for (int kt = 0; kt < 16; kt++) {
        CP_WAIT0();
        __syncthreads();

        if (kt + 1 < 16) {
            int nb = (kt + 1) & 1;
            int k0 = (kt + 1) * 32;
#pragma unroll
            for (int i = 0; i < 4; i++) {
                int f4 = tid + i * 256;
                int r  = f4 >> 3;
                int kq = (f4 & 7) << 2;
                CP16(base_sh + (uint32_t)(nb * PJ_BUF + r * PJSTR + kq) * 4,
                     X + (size_t)(row0 + r) * 512 + k0 + kq);
                CP16(base_sh + (uint32_t)((2 + nb) * PJ_BUF + r * PJSTR + kq) * 4,
                     W + (size_t)(col0 + r) * 512 + k0 + kq);
            }
            CP_COMMIT();
        }

        const float* Xs = psm + (kt & 1) * PJ_BUF;
        const float* Ws = psm + (2 + (kt & 1)) * PJ_BUF;

#pragma unroll
        for (int kk = 0; kk < 32; kk += 8) {
            uint32_t a[2][4];
#pragma unroll
            for (int f = 0; f < 2; f++) {
                int rbase = warp_m * 32 + f * 16 + gid;
#pragma unroll
                for (int rg = 0; rg < 4; rg++) {
                    int r    = rbase + ((rg & 1) << 3);
                    int kcol = kk + tig + ((rg >> 1) << 2);
                    a[f][rg] = rna_u(Xs[r * PJSTR + kcol]);
                }
            }
#pragma unroll
            for (int j = 0; j < 8; j++) {
                int cidx = warp_n * 64 + j * 8 + gid;
                uint32_t b0 = rna_u(Ws[cidx * PJSTR + kk + tig]);
                uint32_t b1 = rna_u(Ws[cidx * PJSTR + kk + tig + 4]);
#pragma unroll
                for (int f = 0; f < 2; f++)
                    MMA_TF32(c[f][j], a[f][0], a[f][1], a[f][2], a[f][3], b0, b1);
            }
        }
    }

    if (sel < 2) {
        // Q/K: float2 head-split stores
#pragma unroll
        for (int f = 0; f < 2; f++) {
            int rloc = warp_m * 32 + f * 16 + gid;
#pragma unroll
            for (int j = 0; j < 8; j++) {
                int cc = col0 + warp_n * 64 + j * 8 + 2 * tig;
#pragma unroll
                for (int h = 0; h < 2; h++) {
                    int r = row0 + rloc + h * 8;
                    int b = r / S, s = r - b * S;
                    int kh = cc >> 6, d = cc & 63;
                    int bk = b * Kk + kh;
                    float tx = to_tf32(c[f][j][h * 2]);
                    float ty = to_tf32(c[f][j][h * 2 + 1]);
                    if (sel == 0)
                        *(float2*)&gq[((size_t)bk * Mm + s) * Dd + d] = make_float2(tx, ty);
                    else
                        *(float2*)&gk[((size_t)bk * SKk + s) * Dd + d] = make_float2(tx, ty);
                }
            }
        }
    } else {
        // V: smem transpose -> coalesced [bk][d][s] stores
        __syncthreads();                       // mainloop reads of psm done
        float* Ts = psm;                       // [128 cols][132 stride]
#pragma unroll
        for (int f = 0; f < 2; f++)
#pragma unroll
            for (int j = 0; j < 8; j++)
#pragma unroll
                for (int h = 0; h < 2; h++) {
                    int rl  = warp_m * 32 + f * 16 + gid + h * 8;
                    int ccl = warp_n * 64 + j * 8 + 2 * tig;
                    Ts[ccl * 132 + rl]       = to_tf32(c[f][j][h * 2]);
                    Ts[(ccl + 1) * 132 + rl] = to_tf32(c[f][j][h * 2 + 1]);
                }
        __syncthreads();
        int b     = row0 / SKk;
        int sbase = row0 - b * SKk;
        int ccl   = tid >> 1;
        int half  = (tid & 1) * 64;
        int cc = col0 + ccl;
        int kh = cc >> 6, d = cc & 63;
        float* dst = gv + ((size_t)(b * Kk + kh) * Dd + d) * SKk + sbase + half;
        const float* srcrow = Ts + ccl * 132 + half;
#pragma unroll
        for (int i = 0; i < 16; i++)
            *(float4*)(dst + i * 4) = *(const float4*)(srcrow + i * 4);
    }
}

// ---------------------------------------------------------------------------
// 3-pass split-tf32 output GEMM: out = g_ctx @ Wo^T  (precision anchor),
// cp.async double-buffered mainloop.
// ---------------------------------------------------------------------------
__global__ __launch_bounds__(256) void proj_out_kernel(
        const float* __restrict__ W, float* __restrict__ Yout) {
    extern __shared__ float psm[];
    const uint32_t base_sh = (uint32_t)__cvta_generic_to_shared(psm);

    const int tid  = threadIdx.x;
    const int lane = tid & 31;
    const int wid  = tid >> 5;
    const int warp_m = wid >> 1;
    const int warp_n = wid & 1;
    const int gid = lane >> 2;
    const int tig = lane & 3;
    const int row0 = blockIdx.x * 128;
    const int col0 = blockIdx.y * 128;

    float c[2][8][4];
#pragma unroll
    for (int f = 0; f < 2; f++)
#pragma unroll
        for (int j = 0; j < 8; j++)
#pragma unroll
            for (int t = 0; t < 4; t++) c[f][j][t] = 0.f;

#pragma unroll
    for (int i = 0; i < 4; i++) {
        int f4 = tid + i * 256;
        int r  = f4 >> 3;
        int kq = (f4 & 7) << 2;
        CP16(base_sh + (uint32_t)(r * PJSTR + kq) * 4,
             g_ctx + (size_t)(row0 + r) * 512 + kq);
        CP16(base_sh + (uint32_t)(2 * PJ_BUF + r * PJSTR + kq) * 4,
             W + (size_t)(col0 + r) * 512 + kq);
    }
    CP_COMMIT();

    for (int kt = 0; kt < 16; kt++) {
        CP_WAIT0();
        __syncthreads();

        if (kt + 1 < 16) {
            int nb = (kt + 1) & 1;
            int k0 = (kt + 1) * 32;
#pragma unroll
            for (int i = 0; i < 4; i++) {
                int f4 = tid + i * 256;
                int r  = f4 >> 3;
                int kq = (f4 & 7) << 2;
                CP16(base_sh + (uint32_t)(nb * PJ_BUF + r * PJSTR + kq) * 4,
                     g_ctx + (size_t)(row0 + r) * 512 + k0 + kq);
                CP16(base_sh + (uint32_t)((2 + nb) * PJ_BUF + r * PJSTR + kq) * 4,
                     W + (size_t)(col0 + r) * 512 + k0 + kq);
            }
            CP_COMMIT();
        }

        const float* Xs = psm + (kt & 1) * PJ_BUF;
        const float* Ws = psm + (2 + (kt & 1)) * PJ_BUF;

#pragma unroll
        for (int kk = 0; kk < 32; kk += 8) {
            uint32_t ahi[2][4], alo[2][4];
#pragma unroll
            for (int f = 0; f < 2; f++) {
                int rbase = warp_m * 32 + f * 16 + gid;
#pragma unroll
                for (int rg = 0; rg < 4; rg++) {
                    int r    = rbase + ((rg & 1) << 3);
                    int kcol = kk + tig + ((rg >> 1) << 2);
                    float x  = Xs[r * PJSTR + kcol];
                    uint32_t hb = __float_as_uint(x) & 0xFFFFE000u;
                    ahi[f][rg] = hb;
                    alo[f][rg] = __float_as_uint(x - __uint_as_float(hb));
                }
            }
#pragma unroll
            for (int j = 0; j < 8; j++) {
                int cidx = warp_n * 64 + j * 8 + gid;
                float b0f = Ws[cidx * PJSTR + kk + tig];
                float b1f = Ws[cidx * PJSTR + kk + tig + 4];
                uint32_t b0h = __float_as_uint(b0f) & 0xFFFFE000u;
                uint32_t b1h = __float_as_uint(b1f) & 0xFFFFE000u;
                uint32_t b0l = __float_as_uint(b0f - __uint_as_float(b0h));
                uint32_t b1l = __float_as_uint(b1f - __uint_as_float(b1h));
#pragma unroll
                for (int f = 0; f < 2; f++) {
                    MMA_TF32(c[f][j], ahi[f][0], ahi[f][1], ahi[f][2], ahi[f][3], b0h, b1h);
                    MMA_TF32(c[f][j], ahi[f][0], ahi[f][1], ahi[f][2], ahi[f][3], b0l, b1l);
                    MMA_TF32(c[f][j], alo[f][0], alo[f][1], alo[f][2], alo[f][3], b0h, b1h);
                }
            }
        }
    }

#pragma unroll
    for (int f = 0; f < 2; f++) {
        int rloc = warp_m * 32 + f * 16 + gid;
#pragma unroll
        for (int j = 0; j < 8; j++) {
            int cc = col0 + warp_n * 64 + j * 8 + 2 * tig;
#pragma unroll
            for (int h = 0; h < 2; h++) {
                int r = row0 + rloc + h * 8;
                *(float2*)(Yout + (size_t)r * 512 + cc) =
                    make_float2(c[f][j][h * 2], c[f][j][h * 2 + 1]);
            }
        }
    }
}

// ---------------------------------------------------------------------------
// Single-pass tf32 MMA banded attention, cp.async pipelined (unchanged R10/11).
// ---------------------------------------------------------------------------
#define QSTR 68
#define KSTR 68
#define VSTR 132
#define PSTR2 132
#define OFF_Q    0
#define OFF_K    (OFF_Q + 64 * QSTR)
#define OFF_PE   (OFF_K + 128 * KSTR)
#define OFF_V    (OFF_PE + 64 * QSTR)
#define OFF_P    (OFF_V + 2 * 64 * VSTR)
#define OFF_SREL (OFF_P + 64 * PSTR2)
#define OFF_SPE  (OFF_SREL + 64 * QSTR)
#define OFF_CORR (OFF_SPE + 64 * QSTR)
#define OFF_LINV (OFF_CORR + 64)
#define ATTN_SMEM_FLOATS (OFF_LINV + 64)

__global__ __launch_bounds__(256) void attn_mma_kernel(
        const float* __restrict__ span_val) {
    extern __shared__ float sm[];
    float* Qs    = sm + OFF_Q;
    float* Ks    = sm + OFF_K;
    float* PEs   = sm + OFF_PE;
    float* Vbase = sm + OFF_V;
    float* Ps    = sm + OFF_P;
    float* Srel  = sm + OFF_SREL;
    float* Spe   = sm + OFF_SPE;
    float* corr_s = sm + OFF_CORR;
    float* linv_s = sm + OFF_LINV;

    const uint32_t* Qu  = (const uint32_t*)Qs;
    const uint32_t* Ku  = (const uint32_t*)Ks;
    const uint32_t* PEu = (const uint32_t*)PEs;
    const uint32_t* Pu  = (const uint32_t*)Ps;

    const int tid  = threadIdx.x;
    const int lane = tid & 31;
    const int wid  = tid >> 5;
    const int gid  = lane >> 2;
    const int tig  = lane & 3;
    const int bk   = blockIdx.y;
    const int i0   = blockIdx.x * 64;
    const int kh   = bk & 7;

    const int mb  = wid & 3;
    const int m0  = mb * 16;
    const int np0 = (wid >> 2) * 32;
    const int jt0 = 2 * mb + 5 * (wid >> 2);

    const int srow = tid >> 2;
    const int tg4  = tid & 3;
    const int tbase = tg4 * 16;
    const float spanL = span_val[kh] * 1024.f;

    const float* gkp_base = gk + ((size_t)bk * SKk + i0) * Dd;
    const float* gvp_base = gv + (size_t)bk * Dd * SKk + i0;

    const int kr  = tid >> 4, kc4 = (tid & 15) << 2;
    const int vd  = tid >> 5, vc4 = (tid & 31) << 2;

    const uint32_t Ksh  = (uint32_t)__cvta_generic_to_shared(Ks);
    const uint32_t PEsh = (uint32_t)__cvta_generic_to_shared(PEs);
    const uint32_t Vsh  = (uint32_t)__cvta_generic_to_shared(Vbase);

    {
        const float* gqp = gq + ((size_t)bk * Mm + i0) * Dd;
#pragma unroll
        for (int it = 0; it < 4; it++) {
            int idx = tid + it * 256;
            int r = idx >> 4, c4 = (idx & 15) << 2;
            float4 v = *(const float4*)(gqp + (size_t)r * Dd + c4);
            v.x *= SCALE; v.y *= SCALE; v.z *= SCALE; v.w *= SCALE;
            *(float4*)&Qs[r * QSTR + c4] = v;
        }
#pragma unroll
        for (int it = 0; it < 33; it++) {
            int idx = tid + it * 256;
            if (idx < 64 * PSTR2) Ps[idx] = 0.f;
        }
#pragma unroll
        for (int it = 0; it < 8; it++) {
            int r = kr + it * 16;
            CP16(Ksh + (uint32_t)(r * KSTR + kc4) * 4,
                 gkp_base + (size_t)r * Dd + kc4);
        }
#pragma unroll
        for (int it = 0; it < 4; it++) {
            int r = kr + it * 16;
            CP16(PEsh + (uint32_t)(r * QSTR + kc4) * 4,
                 gpe + (size_t)r * Dd + kc4);
        }
#pragma unroll
        for (int it = 0; it < 8; it++) {
            int d = vd + it * 8;
            CP16(Vsh + (uint32_t)(d * VSTR + vc4) * 4,
                 gvp_base + (size_t)d * SKk + vc4);
        }
        CP_COMMIT();
    }

    float oacc[4][4];
#pragma unroll
    for (int j = 0; j < 4; j++)
#pragma unroll
        for (int t = 0; t < 4; t++) oacc[j][t] = 0.f;

    float m_run = -1e30f, l_run = 0.f;

    for (int cidx = 0; cidx < 16; cidx++) {
        const int jc = cidx * 64;
        const uint32_t* Vu = (const uint32_t*)(Vbase + (cidx & 1) * 64 * VSTR);

        CP_WAIT0();
        __syncthreads();

        if (cidx + 1 < 16) {
            uint32_t vdst = Vsh + (uint32_t)(((cidx + 1) & 1) * 64 * VSTR) * 4;
            const float* vsrc = gvp_base + (cidx + 1) * 64;
#pragma unroll
            for (int it = 0; it < 8; it++) {
                int d = vd + it * 8;
                CP16(vdst + (uint32_t)(d * VSTR + vc4) * 4,
                     vsrc + (size_t)d * SKk + vc4);
            }
            CP_COMMIT();
        }

        float sacc[5][4], pacc[4][4];
#pragma unroll
        for (int j = 0; j < 5; j++)
#pragma unroll
            for (int t = 0; t < 4; t++) sacc[j][t] = 0.f;
#pragma unroll
        for (int j = 0; j < 4; j++)
#pragma unroll
            for (int t = 0; t < 4; t++) pacc[j][t] = 0.f;

#pragma unroll
        for (int k0 = 0; k0 < 64; k0 += 8) {
            int ar = (m0 + gid) * QSTR + k0 + tig;
            uint32_t a0 = Qu[ar];
            uint32_t a1 = Qu[ar + 8 * QSTR];
            uint32_t a2 = Qu[ar + 4];
            uint32_t a3 = Qu[ar + 8 * QSTR + 4];
#pragma unroll
            for (int jj = 0; jj < 5; jj++) {
                int br = ((jt0 + jj) * 8 + gid) * KSTR + k0 + tig;
                MMA_TF32(sacc[jj], a0, a1, a2, a3, Ku[br], Ku[br + 4]);
            }
#pragma unroll
            for (int j = 0; j < 4; j++) {
                int br = (np0 + 8 * j + gid) * QSTR + k0 + tig;
                MMA_TF32(pacc[j], a0, a1, a2, a3, PEu[br], PEu[br + 4]);
            }
        }

#pragma unroll
        for (int jj = 0; jj < 5; jj++) {
            int col = (jt0 + jj) * 8 + 2 * tig;
            int r0 = m0 + gid, r1 = r0 + 8;
            int t00 = col - r0, t10 = col - r1;
            if ((unsigned)t00 < 64u)       Srel[r0 * QSTR + t00]     = sacc[jj][0];
            if ((unsigned)(t00 + 1) < 64u) Srel[r0 * QSTR + t00 + 1] = sacc[jj][1];
            if ((unsigned)t10 < 64u)       Srel[r1 * QSTR + t10]     = sacc[jj][2];
            if ((unsigned)(t10 + 1) < 64u) Srel[r1 * QSTR + t10 + 1] = sacc[jj][3];
        }
#pragma unroll
        for (int j = 0; j < 4; j++) {
            int col = np0 + 8 * j + 2 * tig;
            Spe[(m0 + gid) * QSTR + col]     = pacc[j][0];
            Spe[(m0 + gid) * QSTR + col + 1] = pacc[j][1];
            Spe[(m0 + gid + 8) * QSTR + col]     = pacc[j][2];
            Spe[(m0 + gid + 8) * QSTR + col + 1] = pacc[j][3];
        }
        __syncthreads();

        if (cidx + 1 < 16) {
            const float* ksrc = gkp_base + (size_t)(cidx + 1) * 64 * Dd;
            const float* psrc = gpe + (size_t)(cidx + 1) * 64 * Dd;
#pragma unroll
            for (int it = 0; it < 8; it++) {
                int r = kr + it * 16;
                CP16(Ksh + (uint32_t)(r * KSTR + kc4) * 4,
                     ksrc + (size_t)r * Dd + kc4);
            }
#pragma unroll
            for (int it = 0; it < 4; it++) {
                int r = kr + it * 16;
                CP16(PEsh + (uint32_t)(r * QSTR + kc4) * 4,
                     psrc + (size_t)r * Dd + kc4);
            }
            CP_COMMIT();
        }

        {
            float s[16];
            float mloc = -1e30f;
#pragma unroll
            for (int e = 0; e < 16; e++) {
                s[e] = Srel[srow * QSTR + tbase + e] + Spe[srow * QSTR + tbase + e];
                mloc = fmaxf(mloc, s[e]);
            }
            mloc = fmaxf(mloc, __shfl_xor_sync(0xFFFFFFFFu, mloc, 1));
            mloc = fmaxf(mloc, __shfl_xor_sync(0xFFFFFFFFu, mloc, 2));
            float m_new = fmaxf(m_run, mloc);
            float corr  = __expf(m_run - m_new);
            l_run *= corr;
            float p[16], psum = 0.f;
#pragma unroll
            for (int e = 0; e < 16; e++) { p[e] = __expf(s[e] - m_new); psum += p[e]; }
            psum += __shfl_xor_sync(0xFFFFFFFFu, psum, 1);
            psum += __shfl_xor_sync(0xFFFFFFFFu, psum, 2);
            l_run += psum;
            m_run = m_new;
            if (tg4 == 0) corr_s[srow] = corr;

#pragma unroll
            for (int e = 0; e < 16; e++) {
                int t = tbase + e;
                float jj = (float)(jc + t);
                float mk = fminf(1.f, fmaxf(0.f, (jj - 1023.f + spanL) * (1.f / 32.f) + 1.f));
                Ps[srow * PSTR2 + srow + t] = to_tf32(p[e] * mk);
            }
        }
        __syncthreads();

        {
            float cA = corr_s[m0 + gid], cB = corr_s[m0 + gid + 8];
#pragma unroll
            for (int j = 0; j < 4; j++) {
                oacc[j][0] *= cA; oacc[j][1] *= cA;
                oacc[j][2] *= cB; oacc[j][3] *= cB;
            }
#pragma unroll
            for (int kk = 0; kk < 10; kk++) {
                int k0 = (2 * mb + kk) * 8;
                int ar = (m0 + gid) * PSTR2 + k0 + tig;
                uint32_t a0 = Pu[ar];
                uint32_t a1 = Pu[ar + 8 * PSTR2];
                uint32_t a2 = Pu[ar + 4];
                uint32_t a3 = Pu[ar + 8 * PSTR2 + 4];
#pragma unroll
                for (int j = 0; j < 4; j++) {
                    int br = (np0 + 8 * j + gid) * VSTR + k0 + tig;
                    MMA_TF32(oacc[j], a0, a1, a2, a3, Vu[br], Vu[br + 4]);
                }
            }
        }
    }

    __syncthreads();
    if (tg4 == 0) linv_s[srow] = 1.f / l_run;
    __syncthreads();

    {
        float lA = linv_s[m0 + gid], lB = linv_s[m0 + gid + 8];
        int b = bk >> 3;
        int r0 = i0 + m0 + gid;
#pragma unroll
        for (int j = 0; j < 4; j++) {
            int col = np0 + 8 * j + 2 * tig;
            float* p0 = g_ctx + ((size_t)(b * Mm + r0) * Kk + kh) * Dd + col;
            float* p1 = g_ctx + ((size_t)(b * Mm + r0 + 8) * Kk + kh) * Dd + col;
            *(float2*)p0 = make_float2(oacc[j][0] * lA, oacc[j][1] * lA);
            *(float2*)p1 = make_float2(oacc[j][2] * lB, oacc[j][3] * lB);
        }
    }
}

// ---------------------------------------------------------------------------
extern "C" void kernel_launch(void* const* d_in, const int* in_sizes, int n_in,
                              void* d_out, int out_size) {
    const float* query = (const float*)d_in[0];
    const float* key   = (const float*)d_in[1];
    const float* value = (const float*)d_in[2];
    const float* pe    = (const float*)d_in[3];
    const float* Wq    = (const float*)d_in[4];
    const float* Wk    = (const float*)d_in[5];
    const float* Wv    = (const float*)d_in[6];
    const float* Wo    = (const float*)d_in[7];
    const float* span  = (const float*)d_in[8];
    float* out = (float*)d_out;

    cudaFuncSetAttribute(attn_mma_kernel,
                         cudaFuncAttributeMaxDynamicSharedMemorySize,
                         ATTN_SMEM_FLOATS * (int)sizeof(float));
    cudaFuncSetAttribute(proj_fused_kernel,
                         cudaFuncAttributeMaxDynamicSharedMemorySize,
                         PROJ_SMEM_FLOATS * (int)sizeof(float));
    cudaFuncSetAttribute(proj_out_kernel,
                         cudaFuncAttributeMaxDynamicSharedMemorySize,
                         PROJ_SMEM_FLOATS * (int)sizeof(float));

    proj_fused_kernel<<<912, 256, PROJ_SMEM_FLOATS * (int)sizeof(float)>>>(
        query, key, value, pe, Wq, Wk, Wv);

    attn_mma_kernel<<<dim3(Mm / 64, BKC), 256,
                      ATTN_SMEM_FLOATS * (int)sizeof(float)>>>(span);

    proj_out_kernel<<<dim3(Bb * Mm / 128, 4), 256,
                      PROJ_SMEM_FLOATS * (int)sizeof(float)>>>(Wo, out);
}

// round 13
// speedup vs baseline: 2.1059x; 1.0763x over previous
#include <cuda_runtime.h>
#include <cuda_bf16.h>
#include <cstdint>

// Problem constants
#define Bb   8
#define Mm   512
#define Ll   1024
#define Hh   512
#define Kk   8
#define Dd   64
#define SKk  1536           // M + L
#define BKC  64             // B * K
#define SCALE 0.125f

// Scratch (device globals)
__device__ float gq[(size_t)BKC * Mm * Dd];      // [bk][s][d]
__device__ float gk[(size_t)BKC * SKk * Dd];     // [bk][s][d]
__device__ float gv[(size_t)BKC * Dd * SKk];     // [bk][d][s]  (transposed)
__device__ float gpe[Ll * Dd];                   // [j][d]
__device__ float g_ctx[(size_t)Bb * Mm * Hh];    // [B, M, K, D]
__device__ float gWr[4 * 512 * 512];             // tf32-rounded Wq,Wk,Wv,Wo

__device__ __forceinline__ float to_tf32(float x) {
    uint32_t r;
    asm("cvt.rna.tf32.f32 %0, %1;" : "=r"(r) : "f"(x));
    return __uint_as_float(r);
}
__device__ __forceinline__ uint32_t rna_u(float x) {
    uint32_t r;
    asm("cvt.rna.tf32.f32 %0, %1;" : "=r"(r) : "f"(x));
    return r;
}

#define MMA_TF32(c, a0, a1, a2, a3, b0, b1)                                   \
    asm volatile(                                                             \
        "mma.sync.aligned.m16n8k8.row.col.f32.tf32.tf32.f32 "                 \
        "{%0,%1,%2,%3},{%4,%5,%6,%7},{%8,%9},{%0,%1,%2,%3};"                  \
        : "+f"(c[0]), "+f"(c[1]), "+f"(c[2]), "+f"(c[3])                      \
        : "r"(a0), "r"(a1), "r"(a2), "r"(a3), "r"(b0), "r"(b1));

#define CP16(dst_sh, src)                                                     \
    asm volatile("cp.async.cg.shared.global [%0], [%1], 16;"                  \
                 :: "r"(dst_sh), "l"(src))
#define CP_COMMIT() asm volatile("cp.async.commit_group;")
#define CP_WAIT0()  asm volatile("cp.async.wait_group 0;" ::: "memory")

#define PJSTR 36
#define PJ_BUF (128 * PJSTR)
#define PROJ_SMEM_FLOATS (4 * PJ_BUF)      // 73,728 B (also fits 128x132 transpose)

// ---------------------------------------------------------------------------
// Weight pre-round: gWr[plane] = tf32(W); rna is idempotent so consumers can
// load raw (bit-identical to per-use cvt).
// ---------------------------------------------------------------------------
__global__ void w_prep_kernel(const float* __restrict__ Wq,
                              const float* __restrict__ Wk,
                              const float* __restrict__ Wv,
                              const float* __restrict__ Wo) {
    int idx4 = (blockIdx.x * 256 + threadIdx.x) * 4;     // grid 1024 -> 1M elems
    int plane = idx4 >> 18;
    int off   = idx4 & 262143;
    const float* W = (plane == 0) ? Wq : (plane == 1) ? Wk
                   : (plane == 2) ? Wv : Wo;
    float4 v = *(const float4*)(W + off);
    v.x = to_tf32(v.x); v.y = to_tf32(v.y);
    v.z = to_tf32(v.z); v.w = to_tf32(v.w);
    *(float4*)(gWr + idx4) = v;
}

// ---------------------------------------------------------------------------
// FUSED single-pass tf32 QKV projection + PE prep. W from gWr (no B cvt).
// blocks 0..127: Q; 128..511: K; 512..895: V (transposed store via smem);
// blocks 896..911: PE transpose prep.
// ---------------------------------------------------------------------------
__global__ __launch_bounds__(256) void proj_fused_kernel(
        const float* __restrict__ query, const float* __restrict__ key,
        const float* __restrict__ value, const float* __restrict__ pe) {
    extern __shared__ float psm[];
    const int bid = blockIdx.x;

    if (bid >= 896) {
        int base = (bid - 896) * 4096 + threadIdx.x;
#pragma unroll
        for (int i = 0; i < 16; i++) {
            int idx = base + i * 256;
            int j = idx >> 6, d = idx & 63;
            gpe[idx] = to_tf32(pe[(size_t)d * Ll + j]);
        }
        return;
    }

    int sel, idx, S;
    const float *X, *W;
    if (bid < 128)      { sel = 0; idx = bid;       X = query; W = gWr;          S = Mm;  }
    else if (bid < 512) { sel = 1; idx = bid - 128; X = key;   W = gWr + 262144; S = SKk; }
    else                { sel = 2; idx = bid - 512; X = value; W = gWr + 524288; S = SKk; }

    const uint32_t base_sh = (uint32_t)__cvta_generic_to_shared(psm);
    const int tid  = threadIdx.x;
    const int lane = tid & 31;
    const int wid  = tid >> 5;
    const int warp_m = wid >> 1;
    const int warp_n = wid & 1;
    const int gid = lane >> 2;
    const int tig = lane & 3;
    const int row0 = (idx >> 2) * 128;
    const int col0 = (idx & 3) * 128;

    float c[2][8][4];
#pragma unroll
    for (int f = 0; f < 2; f++)
#pragma unroll
        for (int j = 0; j < 8; j++)
#pragma unroll
            for (int t = 0; t < 4; t++) c[f][j][t] = 0.f;

#pragma unroll
    for (int i = 0; i < 4; i++) {
        int f4 = tid + i * 256;
        int r  = f4 >> 3;
        int kq = (f4 & 7) << 2;
        CP16(base_sh + (uint32_t)(r * PJSTR + kq) * 4,
             X + (size_t)(row0 + r) * 512 + kq);
        CP16(base_sh + (uint32_t)(2 * PJ_BUF + r * PJSTR + kq) * 4,
             W + (size_t)(col0 + r) * 512 + kq);
    }
    CP_COMMIT();

    for (int kt = 0; kt < 16; kt++) {
        CP_WAIT0();
        __syncthreads();

        if (kt + 1 < 16) {
            int nb = (kt + 1) & 1;
            int k0 = (kt + 1) * 32;
#pragma unroll
            for (int i = 0; i < 4; i++) {
                int f4 = tid + i * 256;
                int r  = f4 >> 3;
                int kq = (f4 & 7) << 2;
                CP16(base_sh + (uint32_t)(nb * PJ_BUF + r * PJSTR + kq) * 4,
                     X + (size_t)(row0 + r) * 512 + k0 + kq);
                CP16(base_sh + (uint32_t)((2 + nb) * PJ_BUF + r * PJSTR + kq) * 4,
                     W + (size_t)(col0 + r) * 512 + k0 + kq);
            }
            CP_COMMIT();
        }

        const float* Xs = psm + (kt & 1) * PJ_BUF;
        const uint32_t* Wsu = (const uint32_t*)(psm + (2 + (kt & 1)) * PJ_BUF);

#pragma unroll
        for (int kk = 0; kk < 32; kk += 8) {
            uint32_t a[2][4];
#pragma unroll
            for (int f = 0; f < 2; f++) {
                int rbase = warp_m * 32 + f * 16 + gid;
#pragma unroll
                for (int rg = 0; rg < 4; rg++) {
                    int r    = rbase + ((rg & 1) << 3);
                    int kcol = kk + tig + ((rg >> 1) << 2);
                    a[f][rg] = rna_u(Xs[r * PJSTR + kcol]);
                }
            }
#pragma unroll
            for (int j = 0; j < 8; j++) {
                int cidx = warp_n * 64 + j * 8 + gid;
                uint32_t b0 = Wsu[cidx * PJSTR + kk + tig];        // pre-rounded
                uint32_t b1 = Wsu[cidx * PJSTR + kk + tig + 4];
#pragma unroll
                for (int f = 0; f < 2; f++)
                    MMA_TF32(c[f][j], a[f][0], a[f][1], a[f][2], a[f][3], b0, b1);
            }
        }
    }

    if (sel < 2) {
#pragma unroll
        for (int f = 0; f < 2; f++) {
            int rloc = warp_m * 32 + f * 16 + gid;
#pragma unroll
            for (int j = 0; j < 8; j++) {
                int cc = col0 + warp_n * 64 + j * 8 + 2 * tig;
#pragma unroll
                for (int h = 0; h < 2; h++) {
                    int r = row0 + rloc + h * 8;
                    int b = r / S, s = r - b * S;
                    int kh = cc >> 6, d = cc & 63;
                    int bk = b * Kk + kh;
                    float tx = to_tf32(c[f][j][h * 2]);
                    float ty = to_tf32(c[f][j][h * 2 + 1]);
                    if (sel == 0)
                        *(float2*)&gq[((size_t)bk * Mm + s) * Dd + d] = make_float2(tx, ty);
                    else
                        *(float2*)&gk[((size_t)bk * SKk + s) * Dd + d] = make_float2(tx, ty);
                }
            }
        }
    } else {
        // V: smem transpose -> coalesced [bk][d][s] stores
        __syncthreads();
        float* Ts = psm;
#pragma unroll
        for (int f = 0; f < 2; f++)
#pragma unroll
            for (int j = 0; j < 8; j++)
#pragma unroll
                for (int h = 0; h < 2; h++) {
                    int rl  = warp_m * 32 + f * 16 + gid + h * 8;
                    int ccl = warp_n * 64 + j * 8 + 2 * tig;
                    Ts[ccl * 132 + rl]       = to_tf32(c[f][j][h * 2]);
                    Ts[(ccl + 1) * 132 + rl] = to_tf32(c[f][j][h * 2 + 1]);
                }
        __syncthreads();
        int b     = row0 / SKk;
        int sbase = row0 - b * SKk;
        int ccl   = tid >> 1;
        int half  = (tid & 1) * 64;
        int cc = col0 + ccl;
        int kh = cc >> 6, d = cc & 63;
        float* dst = gv + ((size_t)(b * Kk + kh) * Dd + d) * SKk + sbase + half;
        const float* srcrow = Ts + ccl * 132 + half;
#pragma unroll
        for (int i = 0; i < 16; i++)
            *(float4*)(dst + i * 4) = *(const float4*)(srcrow + i * 4);
    }
}

// ---------------------------------------------------------------------------
// Single-pass tf32 output GEMM: out = g_ctx @ Wo^T (Wo pre-rounded in gWr[3]).
// cp.async double-buffered mainloop.
// ---------------------------------------------------------------------------
__global__ __launch_bounds__(256) void proj_out_kernel(float* __restrict__ Yout) {
    extern __shared__ float psm[];
    const uint32_t base_sh = (uint32_t)__cvta_generic_to_shared(psm);
    const float* W = gWr + 786432;     // plane 3 = Wo

    const int tid  = threadIdx.x;
    const int lane = tid & 31;
    const int wid  = tid >> 5;
    const int warp_m = wid >> 1;
    const int warp_n = wid & 1;
    const int gid = lane >> 2;
    const int tig = lane & 3;
    const int row0 = blockIdx.x * 128;
    const int col0 = blockIdx.y * 128;

    float c[2][8][4];
#pragma unroll
    for (int f = 0; f < 2; f++)
#pragma unroll
        for (int j = 0; j < 8; j++)
#pragma unroll
            for (int t = 0; t < 4; t++) c[f][j][t] = 0.f;

#pragma unroll
    for (int i = 0; i < 4; i++) {
        int f4 = tid + i * 256;
        int r  = f4 >> 3;
        int kq = (f4 & 7) << 2;
        CP16(base_sh + (uint32_t)(r * PJSTR + kq) * 4,
             g_ctx + (size_t)(row0 + r) * 512 + kq);
        CP16(base_sh + (uint32_t)(2 * PJ_BUF + r * PJSTR + kq) * 4,
             W + (size_t)(col0 + r) * 512 + kq);
    }
    CP_COMMIT();

    for (int kt = 0; kt < 16; kt++) {
        CP_WAIT0();
        __syncthreads();

        if (kt + 1 < 16) {
            int nb = (kt + 1) & 1;
            int k0 = (kt + 1) * 32;
#pragma unroll
            for (int i = 0; i < 4; i++) {
                int f4 = tid + i * 256;
                int r  = f4 >> 3;
                int kq = (f4 & 7) << 2;
                CP16(base_sh + (uint32_t)(nb * PJ_BUF + r * PJSTR + kq) * 4,
                     g_ctx + (size_t)(row0 + r) * 512 + k0 + kq);
                CP16(base_sh + (uint32_t)((2 + nb) * PJ_BUF + r * PJSTR + kq) * 4,
                     W + (size_t)(col0 + r) * 512 + k0 + kq);
            }
            CP_COMMIT();
        }

        const float* Xs = psm + (kt & 1) * PJ_BUF;
        const uint32_t* Wsu = (const uint32_t*)(psm + (2 + (kt & 1)) * PJ_BUF);

#pragma unroll
        for (int kk = 0; kk < 32; kk += 8) {
            uint32_t a[2][4];
#pragma unroll
            for (int f = 0; f < 2; f++) {
                int rbase = warp_m * 32 + f * 16 + gid;
#pragma unroll
                for (int rg = 0; rg < 4; rg++) {
                    int r    = rbase + ((rg & 1) << 3);
                    int kcol = kk + tig + ((rg >> 1) << 2);
                    a[f][rg] = rna_u(Xs[r * PJSTR + kcol]);
                }
            }
#pragma unroll
            for (int j = 0; j < 8; j++) {
                int cidx = warp_n * 64 + j * 8 + gid;
                uint32_t b0 = Wsu[cidx * PJSTR + kk + tig];
                uint32_t b1 = Wsu[cidx * PJSTR + kk + tig + 4];
#pragma unroll
                for (int f = 0; f < 2; f++)
                    MMA_TF32(c[f][j], a[f][0], a[f][1], a[f][2], a[f][3], b0, b1);
            }
        }
    }

#pragma unroll
    for (int f = 0; f < 2; f++) {
        int rloc = warp_m * 32 + f * 16 + gid;
#pragma unroll
        for (int j = 0; j < 8; j++) {
            int cc = col0 + warp_n * 64 + j * 8 + 2 * tig;
#pragma unroll
            for (int h = 0; h < 2; h++) {
                int r = row0 + rloc + h * 8;
                *(float2*)(Yout + (size_t)r * 512 + cc) =
                    make_float2(c[f][j][h * 2], c[f][j][h * 2 + 1]);
            }
        }
    }
}

// ---------------------------------------------------------------------------
// Single-pass tf32 MMA banded attention, cp.async pipelined (unchanged).
// ---------------------------------------------------------------------------
#define QSTR 68
#define KSTR 68
#define VSTR 132
#define PSTR2 132
#define OFF_Q    0
#define OFF_K    (OFF_Q + 64 * QSTR)
#define OFF_PE   (OFF_K + 128 * KSTR)
#define OFF_V    (OFF_PE + 64 * QSTR)
#define OFF_P    (OFF_V + 2 * 64 * VSTR)
#define OFF_SREL (OFF_P + 64 * PSTR2)
#define OFF_SPE  (OFF_SREL + 64 * QSTR)
#define OFF_CORR (OFF_SPE + 64 * QSTR)
#define OFF_LINV (OFF_CORR + 64)
#define ATTN_SMEM_FLOATS (OFF_LINV + 64)

__global__ __launch_bounds__(256) void attn_mma_kernel(
        const float* __restrict__ span_val) {
    extern __shared__ float sm[];
    float* Qs    = sm + OFF_Q;
    float* Ks    = sm + OFF_K;
    float* PEs   = sm + OFF_PE;
    float* Vbase = sm + OFF_V;
    float* Ps    = sm + OFF_P;
    float* Srel  = sm + OFF_SREL;
    float* Spe   = sm + OFF_SPE;
    float* corr_s = sm + OFF_CORR;
    float* linv_s = sm + OFF_LINV;

    const uint32_t* Qu  = (const uint32_t*)Qs;
    const uint32_t* Ku  = (const uint32_t*)Ks;
    const uint32_t* PEu = (const uint32_t*)PEs;
    const uint32_t* Pu  = (const uint32_t*)Ps;

    const int tid  = threadIdx.x;
    const int lane = tid & 31;
    const int wid  = tid >> 5;
    const int gid  = lane >> 2;
    const int tig  = lane & 3;
    const int bk   = blockIdx.y;
    const int i0   = blockIdx.x * 64;
    const int kh   = bk & 7;

    const int mb  = wid & 3;
    const int m0  = mb * 16;
    const int np0 = (wid >> 2) * 32;
    const int jt0 = 2 * mb + 5 * (wid >> 2);

    const int srow = tid >> 2;
    const int tg4  = tid & 3;
    const int tbase = tg4 * 16;
    const float spanL = span_val[kh] * 1024.f;

    const float* gkp_base = gk + ((size_t)bk * SKk + i0) * Dd;
    const float* gvp_base = gv + (size_t)bk * Dd * SKk + i0;

    const int kr  = tid >> 4, kc4 = (tid & 15) << 2;
    const int vd  = tid >> 5, vc4 = (tid & 31) << 2;

    const uint32_t Ksh  = (uint32_t)__cvta_generic_to_shared(Ks);
    const uint32_t PEsh = (uint32_t)__cvta_generic_to_shared(PEs);
    const uint32_t Vsh  = (uint32_t)__cvta_generic_to_shared(Vbase);

    {
        const float* gqp = gq + ((size_t)bk * Mm + i0) * Dd;
#pragma unroll
        for (int it = 0; it < 4; it++) {
            int idx = tid + it * 256;
            int r = idx >> 4, c4 = (idx & 15) << 2;
            float4 v = *(const float4*)(gqp + (size_t)r * Dd + c4);
            v.x *= SCALE; v.y *= SCALE; v.z *= SCALE; v.w *= SCALE;
            *(float4*)&Qs[r * QSTR + c4] = v;
        }
#pragma unroll
        for (int it = 0; it < 33; it++) {
            int idx = tid + it * 256;
            if (idx < 64 * PSTR2) Ps[idx] = 0.f;
        }
#pragma unroll
        for (int it = 0; it < 8; it++) {
            int r = kr + it * 16;
            CP16(Ksh + (uint32_t)(r * KSTR + kc4) * 4,
                 gkp_base + (size_t)r * Dd + kc4);
        }
#pragma unroll
        for (int it = 0; it < 4; it++) {
            int r = kr + it * 16;
            CP16(PEsh + (uint32_t)(r * QSTR + kc4) * 4,
                 gpe + (size_t)r * Dd + kc4);
        }
#pragma unroll
        for (int it = 0; it < 8; it++) {
            int d = vd + it * 8;
            CP16(Vsh + (uint32_t)(d * VSTR + vc4) * 4,
                 gvp_base + (size_t)d * SKk + vc4);
        }
        CP_COMMIT();
    }

    float oacc[4][4];
#pragma unroll
    for (int j = 0; j < 4; j++)
#pragma unroll
        for (int t = 0; t < 4; t++) oacc[j][t] = 0.f;

    float m_run = -1e30f, l_run = 0.f;

    for (int cidx = 0; cidx < 16; cidx++) {
        const int jc = cidx * 64;
        const uint32_t* Vu = (const uint32_t*)(Vbase + (cidx & 1) * 64 * VSTR);

        CP_WAIT0();
        __syncthreads();

        if (cidx + 1 < 16) {
            uint32_t vdst = Vsh + (uint32_t)(((cidx + 1) & 1) * 64 * VSTR) * 4;
            const float* vsrc = gvp_base + (cidx + 1) * 64;
#pragma unroll
            for (int it = 0; it < 8; it++) {
                int d = vd + it * 8;
                CP16(vdst + (uint32_t)(d * VSTR + vc4) * 4,
                     vsrc + (size_t)d * SKk + vc4);
            }
            CP_COMMIT();
        }

        float sacc[5][4], pacc[4][4];
#pragma unroll
        for (int j = 0; j < 5; j++)
#pragma unroll
            for (int t = 0; t < 4; t++) sacc[j][t] = 0.f;
#pragma unroll
        for (int j = 0; j < 4; j++)
#pragma unroll
            for (int t = 0; t < 4; t++) pacc[j][t] = 0.f;

#pragma unroll
        for (int k0 = 0; k0 < 64; k0 += 8) {
            int ar = (m0 + gid) * QSTR + k0 + tig;
            uint32_t a0 = Qu[ar];
            uint32_t a1 = Qu[ar + 8 * QSTR];
            uint32_t a2 = Qu[ar + 4];
            uint32_t a3 = Qu[ar + 8 * QSTR + 4];
#pragma unroll
            for (int jj = 0; jj < 5; jj++) {
                int br = ((jt0 + jj) * 8 + gid) * KSTR + k0 + tig;
                MMA_TF32(sacc[jj], a0, a1, a2, a3, Ku[br], Ku[br + 4]);
            }
#pragma unroll
            for (int j = 0; j < 4; j++) {
                int br = (np0 + 8 * j + gid) * QSTR + k0 + tig;
                MMA_TF32(pacc[j], a0, a1, a2, a3, PEu[br], PEu[br + 4]);
            }
        }

#pragma unroll
        for (int jj = 0; jj < 5; jj++) {
            int col = (jt0 + jj) * 8 + 2 * tig;
            int r0 = m0 + gid, r1 = r0 + 8;
            int t00 = col - r0, t10 = col - r1;
            if ((unsigned)t00 < 64u)       Srel[r0 * QSTR + t00]     = sacc[jj][0];
            if ((unsigned)(t00 + 1) < 64u) Srel[r0 * QSTR + t00 + 1] = sacc[jj][1];
            if ((unsigned)t10 < 64u)       Srel[r1 * QSTR + t10]     = sacc[jj][2];
            if ((unsigned)(t10 + 1) < 64u) Srel[r1 * QSTR + t10 + 1] = sacc[jj][3];
        }
#pragma unroll
        for (int j = 0; j < 4; j++) {
            int col = np0 + 8 * j + 2 * tig;
            Spe[(m0 + gid) * QSTR + col]     = pacc[j][0];
            Spe[(m0 + gid) * QSTR + col + 1] = pacc[j][1];
            Spe[(m0 + gid + 8) * QSTR + col]     = pacc[j][2];
            Spe[(m0 + gid + 8) * QSTR + col + 1] = pacc[j][3];
        }
        __syncthreads();

        if (cidx + 1 < 16) {
            const float* ksrc = gkp_base + (size_t)(cidx + 1) * 64 * Dd;
            const float* psrc = gpe + (size_t)(cidx + 1) * 64 * Dd;
#pragma unroll
            for (int it = 0; it < 8; it++) {
                int r = kr + it * 16;
                CP16(Ksh + (uint32_t)(r * KSTR + kc4) * 4,
                     ksrc + (size_t)r * Dd + kc4);
            }
#pragma unroll
            for (int it = 0; it < 4; it++) {
                int r = kr + it * 16;
                CP16(PEsh + (uint32_t)(r * QSTR + kc4) * 4,
                     psrc + (size_t)r * Dd + kc4);
            }
            CP_COMMIT();
        }

        {
            float s[16];
            float mloc = -1e30f;
#pragma unroll
            for (int e = 0; e < 16; e++) {
                s[e] = Srel[srow * QSTR + tbase + e] + Spe[srow * QSTR + tbase + e];
                mloc = fmaxf(mloc, s[e]);
            }
            mloc = fmaxf(mloc, __shfl_xor_sync(0xFFFFFFFFu, mloc, 1));
            mloc = fmaxf(mloc, __shfl_xor_sync(0xFFFFFFFFu, mloc, 2));
            float m_new = fmaxf(m_run, mloc);
            float corr  = __expf(m_run - m_new);
            l_run *= corr;
            float p[16], psum = 0.f;
#pragma unroll
            for (int e = 0; e < 16; e++) { p[e] = __expf(s[e] - m_new); psum += p[e]; }
            psum += __shfl_xor_sync(0xFFFFFFFFu, psum, 1);
            psum += __shfl_xor_sync(0xFFFFFFFFu, psum, 2);
            l_run += psum;
            m_run = m_new;
            if (tg4 == 0) corr_s[srow] = corr;

#pragma unroll
            for (int e = 0; e < 16; e++) {
                int t = tbase + e;
                float jj = (float)(jc + t);
                float mk = fminf(1.f, fmaxf(0.f, (jj - 1023.f + spanL) * (1.f / 32.f) + 1.f));
                Ps[srow * PSTR2 + srow + t] = to_tf32(p[e] * mk);
            }
        }
        __syncthreads();

        {
            float cA = corr_s[m0 + gid], cB = corr_s[m0 + gid + 8];
#pragma unroll
            for (int j = 0; j < 4; j++) {
                oacc[j][0] *= cA; oacc[j][1] *= cA;
                oacc[j][2] *= cB; oacc[j][3] *= cB;
            }
#pragma unroll
            for (int kk = 0; kk < 10; kk++) {
                int k0 = (2 * mb + kk) * 8;
                int ar = (m0 + gid) * PSTR2 + k0 + tig;
                uint32_t a0 = Pu[ar];
                uint32_t a1 = Pu[ar + 8 * PSTR2];
                uint32_t a2 = Pu[ar + 4];
                uint32_t a3 = Pu[ar + 8 * PSTR2 + 4];
#pragma unroll
                for (int j = 0; j < 4; j++) {
                    int br = (np0 + 8 * j + gid) * VSTR + k0 + tig;
                    MMA_TF32(oacc[j], a0, a1, a2, a3, Vu[br], Vu[br + 4]);
                }
            }
        }
    }

    __syncthreads();
    if (tg4 == 0) linv_s[srow] = 1.f / l_run;
    __syncthreads();

    {
        float lA = linv_s[m0 + gid], lB = linv_s[m0 + gid + 8];
        int b = bk >> 3;
        int r0 = i0 + m0 + gid;
#pragma unroll
        for (int j = 0; j < 4; j++) {
            int col = np0 + 8 * j + 2 * tig;
            float* p0 = g_ctx + ((size_t)(b * Mm + r0) * Kk + kh) * Dd + col;
            float* p1 = g_ctx + ((size_t)(b * Mm + r0 + 8) * Kk + kh) * Dd + col;
            *(float2*)p0 = make_float2(oacc[j][0] * lA, oacc[j][1] * lA);
            *(float2*)p1 = make_float2(oacc[j][2] * lB, oacc[j][3] * lB);
        }
    }
}

// ---------------------------------------------------------------------------
extern "C" void kernel_launch(void* const* d_in, const int* in_sizes, int n_in,
                              void* d_out, int out_size) {
    const float* query = (const float*)d_in[0];
    const float* key   = (const float*)d_in[1];
    const float* value = (const float*)d_in[2];
    const float* pe    = (const float*)d_in[3];
    const float* Wq    = (const float*)d_in[4];
    const float* Wk    = (const float*)d_in[5];
    const float* Wv    = (const float*)d_in[6];
    const float* Wo    = (const float*)d_in[7];
    const float* span  = (const float*)d_in[8];
    float* out = (float*)d_out;

    cudaFuncSetAttribute(attn_mma_kernel,
                         cudaFuncAttributeMaxDynamicSharedMemorySize,
                         ATTN_SMEM_FLOATS * (int)sizeof(float));
    cudaFuncSetAttribute(proj_fused_kernel,
                         cudaFuncAttributeMaxDynamicSharedMemorySize,
                         PROJ_SMEM_FLOATS * (int)sizeof(float));
    cudaFuncSetAttribute(proj_out_kernel,
                         cudaFuncAttributeMaxDynamicSharedMemorySize,
                         PROJ_SMEM_FLOATS * (int)sizeof(float));

    w_prep_kernel<<<1024, 256>>>(Wq, Wk, Wv, Wo);

    proj_fused_kernel<<<912, 256, PROJ_SMEM_FLOATS * (int)sizeof(float)>>>(
        query, key, value, pe);

    attn_mma_kernel<<<dim3(Mm / 64, BKC), 256,
                      ATTN_SMEM_FLOATS * (int)sizeof(float)>>>(span);

    proj_out_kernel<<<dim3(Bb * Mm / 128, 4), 256,
                      PROJ_SMEM_FLOATS * (int)sizeof(float)>>>(out);
}